// round 4
// baseline (speedup 1.0000x reference)
#include <cuda_runtime.h>
#include <cuda_bf16.h>
#include <cstdint>
#include <math.h>

#define S_LEN 4096
#define BATCH 64
#define HSZ   256
#define MROWS (BATCH * S_LEN)   // 262144

// ---------------- device scratch (allocation-free rule) ----------------
__device__ float g_s [(size_t)MROWS * 128];           // s = event@Ve
__device__ float g_x [(size_t)MROWS * 128];           // x
__device__ float g_u [(size_t)MROWS * 128];           // tanh(s@Wef1+bef1)
__device__ float g_xw[(size_t)MROWS * 1024];          // [b][s][4HS] (bias baked in)
__device__ float g_j [(size_t)MROWS * HSZ];           // [b][s][HS]
__device__ float g_h [BATCH * HSZ];                   // final h

__device__ __forceinline__ float sigf(float x) { return 1.0f / (1.0f + expf(-x)); }

__device__ __forceinline__ uint32_t s2u(const void* p) {
    uint32_t r;
    asm("{ .reg .u64 t; cvta.to.shared.u64 t, %1; cvt.u32.u64 %0, t; }"
        : "=r"(r) : "l"(p));
    return r;
}

// ---------------- embeddings: s = ev@Ve ; x = s + 2*(vc@Vc + tanh(vn@Vn)) --
__global__ void __launch_bounds__(256, 1)
k_embed(const float* __restrict__ ev, const float* __restrict__ vc,
        const float* __restrict__ vn, const float* __restrict__ Ve,
        const float* __restrict__ Vc, const float* __restrict__ Vn) {
    extern __shared__ float sm[];
    float* wE  = sm;                 // [64][128]
    float* wC  = sm + 64 * 128;      // [32][128]
    float* wN  = sm + 96 * 128;      // [16][128]
    float* ie  = sm + 112 * 128;     // [32][64]
    float* ic  = ie + 32 * 64;       // [32][32]
    float* inn = ic + 32 * 32;       // [32][16]
    int tid = threadIdx.x;
    size_t rb = (size_t)blockIdx.x * 32;

    for (int i = tid; i < 2048; i += 256) ((float4*)wE)[i]  = ((const float4*)Ve)[i];
    for (int i = tid; i < 1024; i += 256) ((float4*)wC)[i]  = ((const float4*)Vc)[i];
    for (int i = tid; i < 512;  i += 256) ((float4*)wN)[i]  = ((const float4*)Vn)[i];
    for (int i = tid; i < 512;  i += 256) ((float4*)ie)[i]  = ((const float4*)(ev + rb * 64))[i];
    for (int i = tid; i < 256;  i += 256) ((float4*)ic)[i]  = ((const float4*)(vc + rb * 32))[i];
    for (int i = tid; i < 128;  i += 256) ((float4*)inn)[i] = ((const float4*)(vn + rb * 16))[i];
    __syncthreads();

    int ty = tid >> 4, tx = tid & 15;   // rows ty*2+{0,1}, cols tx*8+{0..7}
    float sa[2][8], ta[2][8], xa[2][8];
    #pragma unroll
    for (int r = 0; r < 2; r++)
        #pragma unroll
        for (int j = 0; j < 8; j++) { sa[r][j] = 0.f; ta[r][j] = 0.f; }

    #pragma unroll 4
    for (int k = 0; k < 64; k++) {
        float a0 = ie[(ty * 2) * 64 + k], a1 = ie[(ty * 2 + 1) * 64 + k];
        const float* wr = wE + k * 128 + tx * 8;
        float4 w0 = *(const float4*)wr, w1 = *(const float4*)(wr + 4);
        float w[8] = {w0.x, w0.y, w0.z, w0.w, w1.x, w1.y, w1.z, w1.w};
        #pragma unroll
        for (int j = 0; j < 8; j++) { sa[0][j] += a0 * w[j]; sa[1][j] += a1 * w[j]; }
    }
    #pragma unroll 4
    for (int k = 0; k < 32; k++) {
        float a0 = ic[(ty * 2) * 32 + k], a1 = ic[(ty * 2 + 1) * 32 + k];
        const float* wr = wC + k * 128 + tx * 8;
        float4 w0 = *(const float4*)wr, w1 = *(const float4*)(wr + 4);
        float w[8] = {w0.x, w0.y, w0.z, w0.w, w1.x, w1.y, w1.z, w1.w};
        #pragma unroll
        for (int j = 0; j < 8; j++) { ta[0][j] += a0 * w[j]; ta[1][j] += a1 * w[j]; }
    }
    #pragma unroll
    for (int r = 0; r < 2; r++)
        #pragma unroll
        for (int j = 0; j < 8; j++) { xa[r][j] = 2.f * ta[r][j]; ta[r][j] = 0.f; }
    #pragma unroll 4
    for (int k = 0; k < 16; k++) {
        float a0 = inn[(ty * 2) * 16 + k], a1 = inn[(ty * 2 + 1) * 16 + k];
        const float* wr = wN + k * 128 + tx * 8;
        float4 w0 = *(const float4*)wr, w1 = *(const float4*)(wr + 4);
        float w[8] = {w0.x, w0.y, w0.z, w0.w, w1.x, w1.y, w1.z, w1.w};
        #pragma unroll
        for (int j = 0; j < 8; j++) { ta[0][j] += a0 * w[j]; ta[1][j] += a1 * w[j]; }
    }
    #pragma unroll
    for (int r = 0; r < 2; r++) {
        size_t row = rb + ty * 2 + r;
        float o[8];
        #pragma unroll
        for (int j = 0; j < 8; j++) o[j] = sa[r][j] + xa[r][j] + 2.f * tanhf(ta[r][j]);
        float* sp = g_s + row * 128 + tx * 8;
        float* xp = g_x + row * 128 + tx * 8;
        *(float4*)sp       = make_float4(sa[r][0], sa[r][1], sa[r][2], sa[r][3]);
        *(float4*)(sp + 4) = make_float4(sa[r][4], sa[r][5], sa[r][6], sa[r][7]);
        *(float4*)xp       = make_float4(o[0], o[1], o[2], o[3]);
        *(float4*)(xp + 4) = make_float4(o[4], o[5], o[6], o[7]);
    }
}

// ---------------- generic K=128 GEMM: out = act(A@W + bias) ----------------
__global__ void __launch_bounds__(256)
k_gemm(const float* __restrict__ A, const float* __restrict__ W,
       const float* __restrict__ bias, float* __restrict__ out,
       int N, int act) {
    extern __shared__ float sm[];
    float* As = sm;            // [64][128]
    float* Ws = sm + 64 * 128; // [128][64]
    int tid = threadIdx.x;
    const float4* A4 = (const float4*)A;
    const float4* W4 = (const float4*)W;
    for (int i = tid; i < 2048; i += 256)
        ((float4*)As)[i] = A4[((size_t)blockIdx.x * 64 + (i >> 5)) * 32 + (i & 31)];
    for (int i = tid; i < 2048; i += 256)
        ((float4*)Ws)[i] = W4[(size_t)(i >> 4) * (N >> 2) + blockIdx.y * 16 + (i & 15)];
    __syncthreads();

    int ty = tid >> 4, tx = tid & 15;
    int r0 = ty * 4, c0 = tx * 4;
    float acc[4][4];
    #pragma unroll
    for (int r = 0; r < 4; r++)
        #pragma unroll
        for (int c = 0; c < 4; c++) acc[r][c] = 0.f;

    #pragma unroll 8
    for (int kk = 0; kk < 128; kk += 4) {
        float4 av[4], wv[4];
        #pragma unroll
        for (int r = 0; r < 4; r++) av[r] = *(const float4*)&As[(r0 + r) * 128 + kk];
        #pragma unroll
        for (int i = 0; i < 4; i++) wv[i] = *(const float4*)&Ws[(kk + i) * 64 + c0];
        #pragma unroll
        for (int r = 0; r < 4; r++) {
            acc[r][0] += av[r].x * wv[0].x + av[r].y * wv[1].x + av[r].z * wv[2].x + av[r].w * wv[3].x;
            acc[r][1] += av[r].x * wv[0].y + av[r].y * wv[1].y + av[r].z * wv[2].y + av[r].w * wv[3].y;
            acc[r][2] += av[r].x * wv[0].z + av[r].y * wv[1].z + av[r].z * wv[2].z + av[r].w * wv[3].z;
            acc[r][3] += av[r].x * wv[0].w + av[r].y * wv[1].w + av[r].z * wv[2].w + av[r].w * wv[3].w;
        }
    }

    int colg = blockIdx.y * 64 + c0;
    float4 bv = *(const float4*)&bias[colg];
    #pragma unroll
    for (int r = 0; r < 4; r++) {
        size_t rg = (size_t)blockIdx.x * 64 + r0 + r;
        float v[4] = {acc[r][0] + bv.x, acc[r][1] + bv.y, acc[r][2] + bv.z, acc[r][3] + bv.w};
        if (act == 1) {
            #pragma unroll
            for (int c = 0; c < 4; c++) v[c] = tanhf(v[c]);
        } else if (act == 2) {
            #pragma unroll
            for (int c = 0; c < 4; c++) v[c] = sigf(v[c]);
        }
        *(float4*)&out[rg * N + colg] = make_float4(v[0], v[1], v[2], v[3]);
    }
}

// ---------------- recurrence: 16 clusters of 8 CTAs, DSMEM h exchange ------
// cluster g owns batch rows 4g..4g+3; rank c owns units 32c..32c+31 (4 gates)
__global__ void __launch_bounds__(256, 1) __cluster_dims__(8, 1, 1)
k_recur(const float* __restrict__ h0, const float* __restrict__ c0,
        const float* __restrict__ Wh, const float* __restrict__ Wc) {
    extern __shared__ float sm[];
    float* whs = sm;               // [256][128]  Wh slice
    float* hb0 = sm + 32768;       // [4][256]    h buffer 0
    float* hb1 = hb0 + 1024;       // [4][256]    h buffer 1
    float* pb  = hb1 + 1024;       // [4][128]    split-k partials
    float* gsm = pb + 512;         // [4][128]    gate sums
    unsigned long long* mbar = (unsigned long long*)(gsm + 512); // 2 mbarriers

    int tid   = threadIdx.x;
    int grp   = blockIdx.x >> 3;
    int cslot = blockIdx.x & 7;

    // Wh slice: whs[k*128 + col], col = gate*32 + unit_local
    for (int i = tid; i < 32768; i += 256) {
        int k = i >> 7, col = i & 127, q = col >> 5, ul = col & 31;
        whs[i] = Wh[k * 1024 + q * 256 + cslot * 32 + ul];
    }
    // h(0) into buffer 0 (each CTA holds the full group h locally)
    ((float4*)hb0)[tid] = ((const float4*)(h0 + grp * 1024))[tid];

    uint32_t mbar_a = s2u(mbar);
    if (tid == 0) {
        asm volatile("mbarrier.init.shared.b64 [%0], %1;" :: "r"(mbar_a),     "r"(1024) : "memory");
        asm volatile("mbarrier.init.shared.b64 [%0], %1;" :: "r"(mbar_a + 8), "r"(1024) : "memory");
    }
    __syncthreads();
    asm volatile("barrier.cluster.arrive.aligned;" ::: "memory");
    asm volatile("barrier.cluster.wait.aligned;"   ::: "memory");

    int col = tid & 127, kh = tid >> 7;       // GEMV role
    int gq = col >> 5, gul = col & 31;
    int gcol = gq * 256 + cslot * 32 + gul;   // global gate column

    int erow = tid >> 5, eul = tid & 31;      // elementwise role (tid < 128)
    int egu  = cslot * 32 + eul;              // global unit index
    float c_st = 0.f, wc0 = 0.f, wc1 = 0.f, wc2 = 0.f;
    uint32_t dst0[8], dst1[8], bar0[8], bar1[8];
    if (tid < 128) {
        c_st = c0[(grp * 4 + erow) * 256 + egu];
        wc0 = Wc[egu]; wc1 = Wc[256 + egu]; wc2 = Wc[512 + egu];
        uint32_t off = (uint32_t)((erow * 256 + egu) * 4);
        uint32_t h0a = s2u(hb0) + off, h1a = s2u(hb1) + off;
        #pragma unroll
        for (int pe = 0; pe < 8; pe++) {
            asm("mapa.shared::cluster.u32 %0, %1, %2;" : "=r"(dst0[pe]) : "r"(h0a), "r"(pe));
            asm("mapa.shared::cluster.u32 %0, %1, %2;" : "=r"(dst1[pe]) : "r"(h1a), "r"(pe));
            asm("mapa.shared::cluster.u32 %0, %1, %2;" : "=r"(bar0[pe]) : "r"(mbar_a), "r"(pe));
            asm("mapa.shared::cluster.u32 %0, %1, %2;" : "=r"(bar1[pe]) : "r"(mbar_a + 8), "r"(pe));
        }
    }

    unsigned par0 = 0, par1 = 0;
    for (int t = 0; t < 4096; t++) {
        int p = t & 1;
        const float* hb = p ? hb1 : hb0;

        // prefetch xw (+bias baked in) and j for this step (hides under wait+GEMV)
        float xw0 = 0.f, xw1 = 0.f, xw2 = 0.f, xw3 = 0.f, jv = 0.f;
        if (kh == 0) {
            size_t xb = ((size_t)(grp * 4) * 4096 + t) * 1024 + gcol;
            xw0 = __ldg(g_xw + xb);
            xw1 = __ldg(g_xw + xb + (size_t)4096 * 1024);
            xw2 = __ldg(g_xw + xb + (size_t)2 * 4096 * 1024);
            xw3 = __ldg(g_xw + xb + (size_t)3 * 4096 * 1024);
        }
        if (tid < 128)
            jv = __ldg(g_j + ((size_t)(grp * 4 + erow) * 4096 + t) * 256 + egu);

        // wait for all 8 CTAs' h writes into buffer p (skip t=0: preloaded)
        if (t > 0) {
            uint32_t mb = mbar_a + (p ? 8u : 0u);
            unsigned par = p ? par1 : par0;
            asm volatile(
                "{\n\t.reg .pred P;\n\t"
                "WL%=:\n\t"
                "mbarrier.try_wait.parity.acquire.cluster.shared::cta.b64 P, [%0], %1, 0x989680;\n\t"
                "@P bra WD%=;\n\t"
                "bra WL%=;\n\t"
                "WD%=:\n\t}"
                :: "r"(mb), "r"(par) : "memory");
            if (p) par1 ^= 1; else par0 ^= 1;
        }

        // GEMV: 4 rows x 1 col, half of K per thread, h from LOCAL smem
        float a0 = kh ? 0.f : xw0;
        float a1 = kh ? 0.f : xw1;
        float a2 = kh ? 0.f : xw2;
        float a3 = kh ? 0.f : xw3;
        int k0 = kh * 128;
        #pragma unroll 8
        for (int kk = 0; kk < 128; kk += 4) {
            float4 h0v = *(const float4*)&hb[0 * 256 + k0 + kk];
            float4 h1v = *(const float4*)&hb[1 * 256 + k0 + kk];
            float4 h2v = *(const float4*)&hb[2 * 256 + k0 + kk];
            float4 h3v = *(const float4*)&hb[3 * 256 + k0 + kk];
            const float* wp = whs + (k0 + kk) * 128 + col;
            float w0 = wp[0], w1 = wp[128], w2 = wp[256], w3 = wp[384];
            a0 += h0v.x * w0 + h0v.y * w1 + h0v.z * w2 + h0v.w * w3;
            a1 += h1v.x * w0 + h1v.y * w1 + h1v.z * w2 + h1v.w * w3;
            a2 += h2v.x * w0 + h2v.y * w1 + h2v.z * w2 + h2v.w * w3;
            a3 += h3v.x * w0 + h3v.y * w1 + h3v.z * w2 + h3v.w * w3;
        }
        if (kh) {
            pb[col] = a0; pb[128 + col] = a1; pb[256 + col] = a2; pb[384 + col] = a3;
        }
        __syncthreads();
        if (!kh) {
            gsm[col]       = a0 + pb[col];
            gsm[128 + col] = a1 + pb[128 + col];
            gsm[256 + col] = a2 + pb[256 + col];
            gsm[384 + col] = a3 + pb[384 + col];
        }
        __syncthreads();

        // elementwise LSTM update + DSMEM push of h(t+1)
        if (tid < 128) {
            float G0 = gsm[erow * 128 + eul];
            float G1 = gsm[erow * 128 + 32 + eul];
            float G2 = gsm[erow * 128 + 64 + eul];
            float G3 = gsm[erow * 128 + 96 + eul];
            float cc = c_st;
            float iv = sigf(G0 + cc * wc0);
            float fv = sigf(G1 + cc * wc1);
            float gv = tanhf(G2);
            float ov = sigf(G3 + cc * wc2);
            float chat = fv * cc + iv * gv;
            float cn = jv * chat + (1.f - jv) * cc;
            float hh = ov * tanhf(chat);
            float hprev = hb[erow * 256 + egu];
            float hn = jv * hh + (1.f - jv) * hprev;
            c_st = cn;
            if (t < 4095) {
                // push h(t+1) into buffer 1-p of all 8 CTAs, then arrive
                #pragma unroll
                for (int pe = 0; pe < 8; pe++) {
                    uint32_t d = p ? dst0[pe] : dst1[pe];
                    asm volatile("st.shared::cluster.f32 [%0], %1;"
                                 :: "r"(d), "f"(hn) : "memory");
                }
                #pragma unroll
                for (int pe = 0; pe < 8; pe++) {
                    uint32_t bb = p ? bar0[pe] : bar1[pe];
                    asm volatile(
                        "mbarrier.arrive.release.cluster.shared::cluster.b64 _, [%0];"
                        :: "r"(bb) : "memory");
                }
            } else {
                g_h[(grp * 4 + erow) * 256 + egu] = hn;
            }
        }
    }

    // no CTA may exit while peers' in-flight DSMEM ops could target its smem
    asm volatile("barrier.cluster.arrive.aligned;" ::: "memory");
    asm volatile("barrier.cluster.wait.aligned;"   ::: "memory");
}

// ---------------- final: out = h_T @ Wlin + blin ----------------
__global__ void k_final(const float* __restrict__ Wlin,
                        const float* __restrict__ blin, float* __restrict__ out) {
    __shared__ float hsm[256];
    int b = blockIdx.x, d = threadIdx.x;   // 64 threads
    for (int i = d; i < 256; i += 64) hsm[i] = g_h[b * 256 + i];
    __syncthreads();
    float acc = blin[d];
    #pragma unroll 8
    for (int k = 0; k < 256; k++) acc += hsm[k] * Wlin[k * 64 + d];
    out[b * 64 + d] = acc;
}

// ---------------- launcher ----------------
extern "C" void kernel_launch(void* const* d_in, const int* in_sizes, int n_in,
                              void* d_out, int out_size) {
    (void)in_sizes; (void)n_in; (void)out_size;
    const float* ev   = (const float*)d_in[0];
    const float* vc   = (const float*)d_in[2];
    const float* vn   = (const float*)d_in[3];
    const float* h0   = (const float*)d_in[4];
    const float* c0   = (const float*)d_in[5];
    const float* Wx   = (const float*)d_in[6];
    const float* Wh   = (const float*)d_in[7];
    const float* Wc   = (const float*)d_in[8];
    const float* bias = (const float*)d_in[9];
    const float* Ve   = (const float*)d_in[10];
    const float* Vc   = (const float*)d_in[11];
    const float* Vn   = (const float*)d_in[12];
    const float* Wlin = (const float*)d_in[13];
    const float* blin = (const float*)d_in[14];
    const float* Wef1 = (const float*)d_in[15];
    const float* bef1 = (const float*)d_in[16];
    const float* Wef3 = (const float*)d_in[17];
    const float* bef3 = (const float*)d_in[18];
    float* out = (float*)d_out;

    cudaFuncSetAttribute(k_embed, cudaFuncAttributeMaxDynamicSharedMemorySize, 71680);
    cudaFuncSetAttribute(k_gemm,  cudaFuncAttributeMaxDynamicSharedMemorySize, 65536);
    cudaFuncSetAttribute(k_recur, cudaFuncAttributeMaxDynamicSharedMemorySize, 143392);

    void *ps, *px, *pu, *pxw, *pj;
    cudaGetSymbolAddress(&ps,  g_s);
    cudaGetSymbolAddress(&px,  g_x);
    cudaGetSymbolAddress(&pu,  g_u);
    cudaGetSymbolAddress(&pxw, g_xw);
    cudaGetSymbolAddress(&pj,  g_j);

    k_embed<<<MROWS / 32, 256, 71680>>>(ev, vc, vn, Ve, Vc, Vn);
    // xW = x @ Wx + bias            [M,1024]
    k_gemm<<<dim3(MROWS / 64, 16), 256, 65536>>>((const float*)px, Wx, bias,
                                                 (float*)pxw, 1024, 0);
    // u = tanh(s @ Wef1 + bef1)     [M,128]
    k_gemm<<<dim3(MROWS / 64, 2), 256, 65536>>>((const float*)ps, Wef1, bef1,
                                                (float*)pu, 128, 1);
    // j = sigmoid(u @ Wef3 + bef3)  [M,256]
    k_gemm<<<dim3(MROWS / 64, 4), 256, 65536>>>((const float*)pu, Wef3, bef3,
                                                (float*)pj, 256, 2);
    k_recur<<<128, 256, 143392>>>(h0, c0, Wh, Wc);
    k_final<<<64, 64>>>(Wlin, blin, out);
}

// round 5
// speedup vs baseline: 1.8530x; 1.8530x over previous
#include <cuda_runtime.h>
#include <cuda_bf16.h>
#include <cstdint>
#include <math.h>

#define S_LEN 4096
#define BATCH 64
#define HSZ   256
#define MROWS (BATCH * S_LEN)   // 262144

typedef unsigned long long ull;

// ---------------- device scratch (allocation-free rule) ----------------
__device__ float g_s [(size_t)MROWS * 128];           // s = event@Ve
__device__ float g_x [(size_t)MROWS * 128];           // x
__device__ float g_u [(size_t)MROWS * 128];           // tanh(s@Wef1+bef1)
__device__ float g_xw[(size_t)MROWS * 1024];          // [b][s][4HS] (bias baked in)
__device__ float g_j [(size_t)MROWS * HSZ];           // [b][s][HS]
__device__ float g_h [BATCH * HSZ];                   // final h

__device__ __forceinline__ float sigf(float x) { return 1.0f / (1.0f + expf(-x)); }

__device__ __forceinline__ uint32_t s2u(const void* p) {
    uint32_t r;
    asm("{ .reg .u64 t; cvta.to.shared.u64 t, %1; cvt.u32.u64 %0, t; }"
        : "=r"(r) : "l"(p));
    return r;
}

#define FMA2(d, a, b) \
    asm("fma.rn.f32x2 %0, %1, %2, %0;" : "+l"(d) : "l"(a), "l"(b))

// ---------------- embeddings: s = ev@Ve ; x = s + 2*(vc@Vc + tanh(vn@Vn)) --
__global__ void __launch_bounds__(256, 1)
k_embed(const float* __restrict__ ev, const float* __restrict__ vc,
        const float* __restrict__ vn, const float* __restrict__ Ve,
        const float* __restrict__ Vc, const float* __restrict__ Vn) {
    extern __shared__ float sm[];
    float* wE  = sm;                 // [64][128]
    float* wC  = sm + 64 * 128;      // [32][128]
    float* wN  = sm + 96 * 128;      // [16][128]
    float* ie  = sm + 112 * 128;     // [32][64]
    float* ic  = ie + 32 * 64;       // [32][32]
    float* inn = ic + 32 * 32;       // [32][16]
    int tid = threadIdx.x;
    size_t rb = (size_t)blockIdx.x * 32;

    for (int i = tid; i < 2048; i += 256) ((float4*)wE)[i]  = ((const float4*)Ve)[i];
    for (int i = tid; i < 1024; i += 256) ((float4*)wC)[i]  = ((const float4*)Vc)[i];
    for (int i = tid; i < 512;  i += 256) ((float4*)wN)[i]  = ((const float4*)Vn)[i];
    for (int i = tid; i < 512;  i += 256) ((float4*)ie)[i]  = ((const float4*)(ev + rb * 64))[i];
    for (int i = tid; i < 256;  i += 256) ((float4*)ic)[i]  = ((const float4*)(vc + rb * 32))[i];
    for (int i = tid; i < 128;  i += 256) ((float4*)inn)[i] = ((const float4*)(vn + rb * 16))[i];
    __syncthreads();

    int ty = tid >> 4, tx = tid & 15;
    float sa[2][8], ta[2][8], xa[2][8];
    #pragma unroll
    for (int r = 0; r < 2; r++)
        #pragma unroll
        for (int j = 0; j < 8; j++) { sa[r][j] = 0.f; ta[r][j] = 0.f; }

    #pragma unroll 4
    for (int k = 0; k < 64; k++) {
        float a0 = ie[(ty * 2) * 64 + k], a1 = ie[(ty * 2 + 1) * 64 + k];
        const float* wr = wE + k * 128 + tx * 8;
        float4 w0 = *(const float4*)wr, w1 = *(const float4*)(wr + 4);
        float w[8] = {w0.x, w0.y, w0.z, w0.w, w1.x, w1.y, w1.z, w1.w};
        #pragma unroll
        for (int j = 0; j < 8; j++) { sa[0][j] += a0 * w[j]; sa[1][j] += a1 * w[j]; }
    }
    #pragma unroll 4
    for (int k = 0; k < 32; k++) {
        float a0 = ic[(ty * 2) * 32 + k], a1 = ic[(ty * 2 + 1) * 32 + k];
        const float* wr = wC + k * 128 + tx * 8;
        float4 w0 = *(const float4*)wr, w1 = *(const float4*)(wr + 4);
        float w[8] = {w0.x, w0.y, w0.z, w0.w, w1.x, w1.y, w1.z, w1.w};
        #pragma unroll
        for (int j = 0; j < 8; j++) { ta[0][j] += a0 * w[j]; ta[1][j] += a1 * w[j]; }
    }
    #pragma unroll
    for (int r = 0; r < 2; r++)
        #pragma unroll
        for (int j = 0; j < 8; j++) { xa[r][j] = 2.f * ta[r][j]; ta[r][j] = 0.f; }
    #pragma unroll 4
    for (int k = 0; k < 16; k++) {
        float a0 = inn[(ty * 2) * 16 + k], a1 = inn[(ty * 2 + 1) * 16 + k];
        const float* wr = wN + k * 128 + tx * 8;
        float4 w0 = *(const float4*)wr, w1 = *(const float4*)(wr + 4);
        float w[8] = {w0.x, w0.y, w0.z, w0.w, w1.x, w1.y, w1.z, w1.w};
        #pragma unroll
        for (int j = 0; j < 8; j++) { ta[0][j] += a0 * w[j]; ta[1][j] += a1 * w[j]; }
    }
    #pragma unroll
    for (int r = 0; r < 2; r++) {
        size_t row = rb + ty * 2 + r;
        float o[8];
        #pragma unroll
        for (int j = 0; j < 8; j++) o[j] = sa[r][j] + xa[r][j] + 2.f * tanhf(ta[r][j]);
        float* sp = g_s + row * 128 + tx * 8;
        float* xp = g_x + row * 128 + tx * 8;
        *(float4*)sp       = make_float4(sa[r][0], sa[r][1], sa[r][2], sa[r][3]);
        *(float4*)(sp + 4) = make_float4(sa[r][4], sa[r][5], sa[r][6], sa[r][7]);
        *(float4*)xp       = make_float4(o[0], o[1], o[2], o[3]);
        *(float4*)(xp + 4) = make_float4(o[4], o[5], o[6], o[7]);
    }
}

// ---------------- generic K=128 GEMM: out = act(A@W + bias) ----------------
__global__ void __launch_bounds__(256)
k_gemm(const float* __restrict__ A, const float* __restrict__ W,
       const float* __restrict__ bias, float* __restrict__ out,
       int N, int act) {
    extern __shared__ float sm[];
    float* As = sm;            // [64][128]
    float* Ws = sm + 64 * 128; // [128][64]
    int tid = threadIdx.x;
    const float4* A4 = (const float4*)A;
    const float4* W4 = (const float4*)W;
    for (int i = tid; i < 2048; i += 256)
        ((float4*)As)[i] = A4[((size_t)blockIdx.x * 64 + (i >> 5)) * 32 + (i & 31)];
    for (int i = tid; i < 2048; i += 256)
        ((float4*)Ws)[i] = W4[(size_t)(i >> 4) * (N >> 2) + blockIdx.y * 16 + (i & 15)];
    __syncthreads();

    int ty = tid >> 4, tx = tid & 15;
    int r0 = ty * 4, c0 = tx * 4;
    float acc[4][4];
    #pragma unroll
    for (int r = 0; r < 4; r++)
        #pragma unroll
        for (int c = 0; c < 4; c++) acc[r][c] = 0.f;

    #pragma unroll 8
    for (int kk = 0; kk < 128; kk += 4) {
        float4 av[4], wv[4];
        #pragma unroll
        for (int r = 0; r < 4; r++) av[r] = *(const float4*)&As[(r0 + r) * 128 + kk];
        #pragma unroll
        for (int i = 0; i < 4; i++) wv[i] = *(const float4*)&Ws[(kk + i) * 64 + c0];
        #pragma unroll
        for (int r = 0; r < 4; r++) {
            acc[r][0] += av[r].x * wv[0].x + av[r].y * wv[1].x + av[r].z * wv[2].x + av[r].w * wv[3].x;
            acc[r][1] += av[r].x * wv[0].y + av[r].y * wv[1].y + av[r].z * wv[2].y + av[r].w * wv[3].y;
            acc[r][2] += av[r].x * wv[0].z + av[r].y * wv[1].z + av[r].z * wv[2].z + av[r].w * wv[3].z;
            acc[r][3] += av[r].x * wv[0].w + av[r].y * wv[1].w + av[r].z * wv[2].w + av[r].w * wv[3].w;
        }
    }

    int colg = blockIdx.y * 64 + c0;
    float4 bv = *(const float4*)&bias[colg];
    #pragma unroll
    for (int r = 0; r < 4; r++) {
        size_t rg = (size_t)blockIdx.x * 64 + r0 + r;
        float v[4] = {acc[r][0] + bv.x, acc[r][1] + bv.y, acc[r][2] + bv.z, acc[r][3] + bv.w};
        if (act == 1) {
            #pragma unroll
            for (int c = 0; c < 4; c++) v[c] = tanhf(v[c]);
        } else if (act == 2) {
            #pragma unroll
            for (int c = 0; c < 4; c++) v[c] = sigf(v[c]);
        }
        *(float4*)&out[rg * N + colg] = make_float4(v[0], v[1], v[2], v[3]);
    }
}

// ---------------- recurrence: 16 clusters of 8 CTAs ------------------------
// cluster g owns batch rows 4g..4g+3; rank c owns units 32c..32c+31 (4 gates)
// h buffers laid out [block(8)][row(4)][unit(32)] so each CTA's contribution
// is one contiguous 512B chunk -> ONE bulk DSMEM copy per peer per step.
__global__ void __launch_bounds__(256, 1) __cluster_dims__(8, 1, 1)
k_recur(const float* __restrict__ h0, const float* __restrict__ c0,
        const float* __restrict__ Wh, const float* __restrict__ Wc) {
    __shared__ float hb0[1024];      // h buffer 0  [blk][row][32]
    __shared__ float hb1[1024];      // h buffer 1
    __shared__ float pb[1024];       // [kh(2)][col(128)][row(4)]
    __shared__ float hstage[256];    // [phase(2)][row(4)][unit(32)]
    __shared__ ull   mbars[2];

    int tid   = threadIdx.x;
    int grp   = blockIdx.x >> 3;
    int cslot = blockIdx.x & 7;

    int col = tid & 127, kh = tid >> 7;       // GEMV role: 4 rows x 1 col x K/2
    int gq = col >> 5, gul = col & 31;
    int gcol = gq * 256 + cslot * 32 + gul;   // global gate column

    // Wh slice in REGISTERS: 64 f32x2 pairs along K
    ull w2[64];
    {
        const float* whp = Wh + gcol;
        #pragma unroll
        for (int i = 0; i < 64; i++) {
            int k = kh * 128 + 2 * i;
            float wlo = __ldg(whp + (size_t)k * 1024);
            float whi = __ldg(whp + (size_t)(k + 1) * 1024);
            asm("mov.b64 %0, {%1, %2};" : "=l"(w2[i]) : "f"(wlo), "f"(whi));
        }
    }

    // h(0) into buffer 0, [blk][row][32] layout
    for (int i = tid; i < 1024; i += 256) {
        int blk = i >> 7, row = (i >> 5) & 3, u = i & 31;
        hb0[i] = h0[grp * 1024 + row * 256 + blk * 32 + u];
    }

    uint32_t mbar_a = s2u(mbars);
    uint32_t hb0_a  = s2u(hb0);
    uint32_t hb1_a  = s2u(hb1);
    uint32_t hst_a  = s2u(hstage);
    if (tid == 0) {
        asm volatile("mbarrier.init.shared.b64 [%0], %1;" :: "r"(mbar_a),     "r"(1) : "memory");
        asm volatile("mbarrier.init.shared.b64 [%0], %1;" :: "r"(mbar_a + 8), "r"(1) : "memory");
        // arm both barriers: 1 arrival + 4096 tx bytes per phase
        asm volatile("mbarrier.arrive.expect_tx.shared.b64 _, [%0], %1;"
                     :: "r"(mbar_a), "r"(4096) : "memory");
        asm volatile("mbarrier.arrive.expect_tx.shared.b64 _, [%0], %1;"
                     :: "r"(mbar_a + 8), "r"(4096) : "memory");
    }
    __syncthreads();
    asm volatile("barrier.cluster.arrive.aligned;" ::: "memory");
    asm volatile("barrier.cluster.wait.aligned;"   ::: "memory");

    int erow = tid >> 5, eul = tid & 31;      // elementwise role (tid < 128)
    int egu  = cslot * 32 + eul;              // global unit index
    float c_st = 0.f, wc0 = 0.f, wc1 = 0.f, wc2 = 0.f;
    if (tid < 128) {
        c_st = c0[(grp * 4 + erow) * 256 + egu];
        wc0 = Wc[egu]; wc1 = Wc[256 + egu]; wc2 = Wc[512 + egu];
    }

    unsigned par0 = 0, par1 = 0;
    for (int t = 0; t < 4096; t++) {
        int p = t & 1;
        const float* hb = p ? hb1 : hb0;

        // prefetch xw (+bias baked in) and j (hides under wait+GEMV)
        float xw0 = 0.f, xw1 = 0.f, xw2 = 0.f, xw3 = 0.f, jv = 0.f;
        if (tid < 128) {
            size_t xb = ((size_t)(grp * 4) * 4096 + t) * 1024 + gcol;
            xw0 = __ldg(g_xw + xb);
            xw1 = __ldg(g_xw + xb + (size_t)4096 * 1024);
            xw2 = __ldg(g_xw + xb + (size_t)2 * 4096 * 1024);
            xw3 = __ldg(g_xw + xb + (size_t)3 * 4096 * 1024);
            jv  = __ldg(g_j + ((size_t)(grp * 4 + erow) * 4096 + t) * 256 + egu);
        }

        // wait for this step's h buffer (skip t=0: preloaded)
        if (t > 0) {
            uint32_t mb = mbar_a + (p ? 8u : 0u);
            unsigned par = p ? par1 : par0;
            asm volatile(
                "{\n\t.reg .pred P;\n\t"
                "WL%=:\n\t"
                "mbarrier.try_wait.parity.acquire.cta.shared::cta.b64 P, [%0], %1, 0x989680;\n\t"
                "@P bra WD%=;\n\t"
                "bra WL%=;\n\t"
                "WD%=:\n\t}"
                :: "r"(mb), "r"(par) : "memory");
            if (p) par1 ^= 1; else par0 ^= 1;
            if (tid == 0)   // re-arm for next phase of this barrier
                asm volatile("mbarrier.arrive.expect_tx.shared.b64 _, [%0], %1;"
                             :: "r"(mb), "r"(4096) : "memory");
        }

        // GEMV: packed f32x2, weights in registers, h broadcast from smem
        ull acc0 = 0ull, acc1 = 0ull, acc2 = 0ull, acc3 = 0ull;
        #pragma unroll
        for (int b = 0; b < 4; b++) {
            const float* base = hb + (kh * 4 + b) * 128;
            #pragma unroll
            for (int kk = 0; kk < 32; kk += 2) {
                ull w  = w2[b * 16 + (kk >> 1)];
                ull h0v = *(const ull*)(base + kk);
                ull h1v = *(const ull*)(base + 32 + kk);
                ull h2v = *(const ull*)(base + 64 + kk);
                ull h3v = *(const ull*)(base + 96 + kk);
                FMA2(acc0, h0v, w);
                FMA2(acc1, h1v, w);
                FMA2(acc2, h2v, w);
                FMA2(acc3, h3v, w);
            }
        }
        float a0, a1, a2, a3;
        {
            float lo, hi;
            asm("mov.b64 {%0, %1}, %2;" : "=f"(lo), "=f"(hi) : "l"(acc0)); a0 = lo + hi + xw0;
            asm("mov.b64 {%0, %1}, %2;" : "=f"(lo), "=f"(hi) : "l"(acc1)); a1 = lo + hi + xw1;
            asm("mov.b64 {%0, %1}, %2;" : "=f"(lo), "=f"(hi) : "l"(acc2)); a2 = lo + hi + xw2;
            asm("mov.b64 {%0, %1}, %2;" : "=f"(lo), "=f"(hi) : "l"(acc3)); a3 = lo + hi + xw3;
        }
        *(float4*)&pb[(kh * 128 + col) * 4] = make_float4(a0, a1, a2, a3);
        __syncthreads();

        // elementwise LSTM update (threads 0..127), stage h(t+1) locally
        if (tid < 128) {
            float G0 = pb[(0 * 32 + eul) * 4 + erow] + pb[(512 + (0 * 32 + eul) * 4) + erow];
            float G1 = pb[(1 * 32 + eul) * 4 + erow] + pb[(512 + (1 * 32 + eul) * 4) + erow];
            float G2 = pb[(2 * 32 + eul) * 4 + erow] + pb[(512 + (2 * 32 + eul) * 4) + erow];
            float G3 = pb[(3 * 32 + eul) * 4 + erow] + pb[(512 + (3 * 32 + eul) * 4) + erow];
            float cc = c_st;
            float iv = sigf(G0 + cc * wc0);
            float fv = sigf(G1 + cc * wc1);
            float gv = tanhf(G2);
            float ov = sigf(G3 + cc * wc2);
            float chat = fv * cc + iv * gv;
            float cn = jv * chat + (1.f - jv) * cc;
            float hh = ov * tanhf(chat);
            float hprev = hb[cslot * 128 + erow * 32 + eul];
            float hn = jv * hh + (1.f - jv) * hprev;
            c_st = cn;
            if (t < 4095)
                hstage[(1 - p) * 128 + tid] = hn;
            else
                g_h[(grp * 4 + erow) * 256 + egu] = hn;
        }
        __syncthreads();

        // ONE thread pushes the CTA's 512B chunk to all 8 CTAs (incl. self)
        if (t < 4095 && tid == 0) {
            asm volatile("fence.proxy.async.shared::cta;" ::: "memory");
            uint32_t src  = hst_a + (uint32_t)((1 - p) * 512);
            uint32_t dstl = (p ? hb0_a : hb1_a) + (uint32_t)(cslot * 512);
            uint32_t mbl  = mbar_a + (p ? 0u : 8u);   // barrier of buffer 1-p
            #pragma unroll
            for (int pe = 0; pe < 8; pe++) {
                uint32_t dst, mbr;
                asm("mapa.shared::cluster.u32 %0, %1, %2;" : "=r"(dst) : "r"(dstl), "r"(pe));
                asm("mapa.shared::cluster.u32 %0, %1, %2;" : "=r"(mbr) : "r"(mbl),  "r"(pe));
                asm volatile(
                    "cp.async.bulk.shared::cluster.shared::cta.mbarrier::complete_tx::bytes "
                    "[%0], [%1], %2, [%3];"
                    :: "r"(dst), "r"(src), "r"(512), "r"(mbr) : "memory");
            }
        }
    }

    asm volatile("barrier.cluster.arrive.aligned;" ::: "memory");
    asm volatile("barrier.cluster.wait.aligned;"   ::: "memory");
}

// ---------------- final: out = h_T @ Wlin + blin ----------------
__global__ void k_final(const float* __restrict__ Wlin,
                        const float* __restrict__ blin, float* __restrict__ out) {
    __shared__ float hsm[256];
    int b = blockIdx.x, d = threadIdx.x;   // 64 threads
    for (int i = d; i < 256; i += 64) hsm[i] = g_h[b * 256 + i];
    __syncthreads();
    float acc = blin[d];
    #pragma unroll 8
    for (int k = 0; k < 256; k++) acc += hsm[k] * Wlin[k * 64 + d];
    out[b * 64 + d] = acc;
}

// ---------------- launcher ----------------
extern "C" void kernel_launch(void* const* d_in, const int* in_sizes, int n_in,
                              void* d_out, int out_size) {
    (void)in_sizes; (void)n_in; (void)out_size;
    const float* ev   = (const float*)d_in[0];
    const float* vc   = (const float*)d_in[2];
    const float* vn   = (const float*)d_in[3];
    const float* h0   = (const float*)d_in[4];
    const float* c0   = (const float*)d_in[5];
    const float* Wx   = (const float*)d_in[6];
    const float* Wh   = (const float*)d_in[7];
    const float* Wc   = (const float*)d_in[8];
    const float* bias = (const float*)d_in[9];
    const float* Ve   = (const float*)d_in[10];
    const float* Vc   = (const float*)d_in[11];
    const float* Vn   = (const float*)d_in[12];
    const float* Wlin = (const float*)d_in[13];
    const float* blin = (const float*)d_in[14];
    const float* Wef1 = (const float*)d_in[15];
    const float* bef1 = (const float*)d_in[16];
    const float* Wef3 = (const float*)d_in[17];
    const float* bef3 = (const float*)d_in[18];
    float* out = (float*)d_out;

    cudaFuncSetAttribute(k_embed, cudaFuncAttributeMaxDynamicSharedMemorySize, 71680);
    cudaFuncSetAttribute(k_gemm,  cudaFuncAttributeMaxDynamicSharedMemorySize, 65536);

    void *ps, *px, *pu, *pxw, *pj;
    cudaGetSymbolAddress(&ps,  g_s);
    cudaGetSymbolAddress(&px,  g_x);
    cudaGetSymbolAddress(&pu,  g_u);
    cudaGetSymbolAddress(&pxw, g_xw);
    cudaGetSymbolAddress(&pj,  g_j);

    k_embed<<<MROWS / 32, 256, 71680>>>(ev, vc, vn, Ve, Vc, Vn);
    // xW = x @ Wx + bias            [M,1024]
    k_gemm<<<dim3(MROWS / 64, 16), 256, 65536>>>((const float*)px, Wx, bias,
                                                 (float*)pxw, 1024, 0);
    // u = tanh(s @ Wef1 + bef1)     [M,128]
    k_gemm<<<dim3(MROWS / 64, 2), 256, 65536>>>((const float*)ps, Wef1, bef1,
                                                (float*)pu, 128, 1);
    // j = sigmoid(u @ Wef3 + bef3)  [M,256]
    k_gemm<<<dim3(MROWS / 64, 4), 256, 65536>>>((const float*)pu, Wef3, bef3,
                                                (float*)pj, 256, 2);
    k_recur<<<128, 256>>>(h0, c0, Wh, Wc);
    k_final<<<64, 64>>>(Wlin, blin, out);
}

// round 6
// speedup vs baseline: 2.2290x; 1.2029x over previous
#include <cuda_runtime.h>
#include <cuda_bf16.h>
#include <cstdint>
#include <math.h>

#define S_LEN 4096
#define BATCH 64
#define HSZ   256
#define MROWS (BATCH * S_LEN)   // 262144

typedef unsigned long long ull;

// ---------------- device scratch (allocation-free rule) ----------------
__device__ float g_s [(size_t)MROWS * 128];           // s = event@Ve
__device__ float g_x [(size_t)MROWS * 128];           // x
__device__ float g_u [(size_t)MROWS * 128];           // tanh(s@Wef1+bef1)
__device__ float g_xw[(size_t)MROWS * 1024];          // [b][s][4HS] (bias baked in)
__device__ float g_j [(size_t)MROWS * HSZ];           // [b][s][HS]
__device__ float g_h [BATCH * HSZ];                   // final h

// fast activations: MUFU-based, saturate correctly at +-inf
__device__ __forceinline__ float sigf(float x) {
    return __fdividef(1.0f, 1.0f + __expf(-x));
}
__device__ __forceinline__ float tanhfast(float x) {
    return 1.0f - __fdividef(2.0f, __expf(2.0f * x) + 1.0f);
}

__device__ __forceinline__ uint32_t s2u(const void* p) {
    uint32_t r;
    asm("{ .reg .u64 t; cvta.to.shared.u64 t, %1; cvt.u32.u64 %0, t; }"
        : "=r"(r) : "l"(p));
    return r;
}

#define FMA2(d, a, b) \
    asm("fma.rn.f32x2 %0, %1, %2, %0;" : "+l"(d) : "l"(a), "l"(b))
#define PACK2(d, a) \
    asm("mov.b64 %0, {%1, %1};" : "=l"(d) : "f"(a))

// ---------------- embeddings: s = ev@Ve ; x = s + 2*(vc@Vc + tanh(vn@Vn)) --
__global__ void __launch_bounds__(256, 1)
k_embed(const float* __restrict__ ev, const float* __restrict__ vc,
        const float* __restrict__ vn, const float* __restrict__ Ve,
        const float* __restrict__ Vc, const float* __restrict__ Vn) {
    extern __shared__ float sm[];
    float* wE  = sm;                 // [64][128]
    float* wC  = sm + 64 * 128;      // [32][128]
    float* wN  = sm + 96 * 128;      // [16][128]
    float* ie  = sm + 112 * 128;     // [32][64]
    float* ic  = ie + 32 * 64;       // [32][32]
    float* inn = ic + 32 * 32;       // [32][16]
    int tid = threadIdx.x;
    size_t rb = (size_t)blockIdx.x * 32;

    for (int i = tid; i < 2048; i += 256) ((float4*)wE)[i]  = ((const float4*)Ve)[i];
    for (int i = tid; i < 1024; i += 256) ((float4*)wC)[i]  = ((const float4*)Vc)[i];
    for (int i = tid; i < 512;  i += 256) ((float4*)wN)[i]  = ((const float4*)Vn)[i];
    for (int i = tid; i < 512;  i += 256) ((float4*)ie)[i]  = ((const float4*)(ev + rb * 64))[i];
    for (int i = tid; i < 256;  i += 256) ((float4*)ic)[i]  = ((const float4*)(vc + rb * 32))[i];
    for (int i = tid; i < 128;  i += 256) ((float4*)inn)[i] = ((const float4*)(vn + rb * 16))[i];
    __syncthreads();

    int ty = tid >> 4, tx = tid & 15;
    float sa[2][8], ta[2][8], xa[2][8];
    #pragma unroll
    for (int r = 0; r < 2; r++)
        #pragma unroll
        for (int j = 0; j < 8; j++) { sa[r][j] = 0.f; ta[r][j] = 0.f; }

    #pragma unroll 4
    for (int k = 0; k < 64; k++) {
        float a0 = ie[(ty * 2) * 64 + k], a1 = ie[(ty * 2 + 1) * 64 + k];
        const float* wr = wE + k * 128 + tx * 8;
        float4 w0 = *(const float4*)wr, w1 = *(const float4*)(wr + 4);
        float w[8] = {w0.x, w0.y, w0.z, w0.w, w1.x, w1.y, w1.z, w1.w};
        #pragma unroll
        for (int j = 0; j < 8; j++) { sa[0][j] += a0 * w[j]; sa[1][j] += a1 * w[j]; }
    }
    #pragma unroll 4
    for (int k = 0; k < 32; k++) {
        float a0 = ic[(ty * 2) * 32 + k], a1 = ic[(ty * 2 + 1) * 32 + k];
        const float* wr = wC + k * 128 + tx * 8;
        float4 w0 = *(const float4*)wr, w1 = *(const float4*)(wr + 4);
        float w[8] = {w0.x, w0.y, w0.z, w0.w, w1.x, w1.y, w1.z, w1.w};
        #pragma unroll
        for (int j = 0; j < 8; j++) { ta[0][j] += a0 * w[j]; ta[1][j] += a1 * w[j]; }
    }
    #pragma unroll
    for (int r = 0; r < 2; r++)
        #pragma unroll
        for (int j = 0; j < 8; j++) { xa[r][j] = 2.f * ta[r][j]; ta[r][j] = 0.f; }
    #pragma unroll 4
    for (int k = 0; k < 16; k++) {
        float a0 = inn[(ty * 2) * 16 + k], a1 = inn[(ty * 2 + 1) * 16 + k];
        const float* wr = wN + k * 128 + tx * 8;
        float4 w0 = *(const float4*)wr, w1 = *(const float4*)(wr + 4);
        float w[8] = {w0.x, w0.y, w0.z, w0.w, w1.x, w1.y, w1.z, w1.w};
        #pragma unroll
        for (int j = 0; j < 8; j++) { ta[0][j] += a0 * w[j]; ta[1][j] += a1 * w[j]; }
    }
    #pragma unroll
    for (int r = 0; r < 2; r++) {
        size_t row = rb + ty * 2 + r;
        float o[8];
        #pragma unroll
        for (int j = 0; j < 8; j++) o[j] = sa[r][j] + xa[r][j] + 2.f * tanhfast(ta[r][j]);
        float* sp = g_s + row * 128 + tx * 8;
        float* xp = g_x + row * 128 + tx * 8;
        *(float4*)sp       = make_float4(sa[r][0], sa[r][1], sa[r][2], sa[r][3]);
        *(float4*)(sp + 4) = make_float4(sa[r][4], sa[r][5], sa[r][6], sa[r][7]);
        *(float4*)xp       = make_float4(o[0], o[1], o[2], o[3]);
        *(float4*)(xp + 4) = make_float4(o[4], o[5], o[6], o[7]);
    }
}

// ---------------- generic K=128 GEMM (f32x2): out = act(A@W + bias) --------
__global__ void __launch_bounds__(256)
k_gemm(const float* __restrict__ A, const float* __restrict__ W,
       const float* __restrict__ bias, float* __restrict__ out,
       int N, int act) {
    extern __shared__ float sm[];
    float* As = sm;            // [64][128]
    float* Ws = sm + 64 * 128; // [128][64]
    int tid = threadIdx.x;
    const float4* A4 = (const float4*)A;
    const float4* W4 = (const float4*)W;
    for (int i = tid; i < 2048; i += 256)
        ((float4*)As)[i] = A4[((size_t)blockIdx.x * 64 + (i >> 5)) * 32 + (i & 31)];
    for (int i = tid; i < 2048; i += 256)
        ((float4*)Ws)[i] = W4[(size_t)(i >> 4) * (N >> 2) + blockIdx.y * 16 + (i & 15)];
    __syncthreads();

    int ty = tid >> 4, tx = tid & 15;
    int r0 = ty * 4, c0 = tx * 4;
    ull acc[4][2];
    #pragma unroll
    for (int r = 0; r < 4; r++) { acc[r][0] = 0ull; acc[r][1] = 0ull; }

    #pragma unroll 4
    for (int kk = 0; kk < 128; kk += 4) {
        float4 av[4];
        ulonglong2 wv[4];
        #pragma unroll
        for (int r = 0; r < 4; r++) av[r] = *(const float4*)&As[(r0 + r) * 128 + kk];
        #pragma unroll
        for (int i = 0; i < 4; i++) wv[i] = *(const ulonglong2*)&Ws[(kk + i) * 64 + c0];
        #pragma unroll
        for (int r = 0; r < 4; r++) {
            ull ad;
            PACK2(ad, av[r].x); FMA2(acc[r][0], ad, wv[0].x); FMA2(acc[r][1], ad, wv[0].y);
            PACK2(ad, av[r].y); FMA2(acc[r][0], ad, wv[1].x); FMA2(acc[r][1], ad, wv[1].y);
            PACK2(ad, av[r].z); FMA2(acc[r][0], ad, wv[2].x); FMA2(acc[r][1], ad, wv[2].y);
            PACK2(ad, av[r].w); FMA2(acc[r][0], ad, wv[3].x); FMA2(acc[r][1], ad, wv[3].y);
        }
    }

    int colg = blockIdx.y * 64 + c0;
    float4 bv = *(const float4*)&bias[colg];
    #pragma unroll
    for (int r = 0; r < 4; r++) {
        size_t rg = (size_t)blockIdx.x * 64 + r0 + r;
        float v[4];
        asm("mov.b64 {%0, %1}, %2;" : "=f"(v[0]), "=f"(v[1]) : "l"(acc[r][0]));
        asm("mov.b64 {%0, %1}, %2;" : "=f"(v[2]), "=f"(v[3]) : "l"(acc[r][1]));
        v[0] += bv.x; v[1] += bv.y; v[2] += bv.z; v[3] += bv.w;
        if (act == 1) {
            #pragma unroll
            for (int c = 0; c < 4; c++) v[c] = tanhfast(v[c]);
        } else if (act == 2) {
            #pragma unroll
            for (int c = 0; c < 4; c++) v[c] = sigf(v[c]);
        }
        *(float4*)&out[rg * N + colg] = make_float4(v[0], v[1], v[2], v[3]);
    }
}

// ---------------- recurrence: 16 clusters of 8 CTAs, 512 threads ----------
// cluster g owns batch rows 4g..4g+3; rank c owns units 32c..32c+31 (4 gates)
// h buffers laid out [block(8)][row(4)][unit(32)]: each CTA's contribution is
// one contiguous 512B chunk -> ONE bulk DSMEM copy per peer per step.
__global__ void __launch_bounds__(512, 1) __cluster_dims__(8, 1, 1)
k_recur(const float* __restrict__ h0, const float* __restrict__ c0,
        const float* __restrict__ Wh, const float* __restrict__ Wc) {
    __shared__ float hb0[1024];      // h buffer 0  [blk][row][32]
    __shared__ float hb1[1024];      // h buffer 1
    __shared__ float pb[2048];       // [kh(4)][col(128)][row(4)]
    __shared__ float hstage[256];    // [phase(2)][row(4)][unit(32)]
    __shared__ ull   mbars[2];

    int tid   = threadIdx.x;
    int grp   = blockIdx.x >> 3;
    int cslot = blockIdx.x & 7;

    int col = tid & 127, kh = tid >> 7;       // kh in 0..3: K-quarter
    int gq = col >> 5, gul = col & 31;
    int gcol = gq * 256 + cslot * 32 + gul;   // global gate column

    // Wh slice in registers: 32 f32x2 pairs covering K-quarter kh
    ull w2[32];
    {
        const float* whp = Wh + gcol;
        #pragma unroll
        for (int i = 0; i < 32; i++) {
            int k = kh * 64 + 2 * i;
            float wlo = __ldg(whp + (size_t)k * 1024);
            float whi = __ldg(whp + (size_t)(k + 1) * 1024);
            asm("mov.b64 %0, {%1, %2};" : "=l"(w2[i]) : "f"(wlo), "f"(whi));
        }
    }

    // h(0) into buffer 0, [blk][row][32] layout
    for (int i = tid; i < 1024; i += 512) {
        int blk = i >> 7, row = (i >> 5) & 3, u = i & 31;
        hb0[i] = h0[grp * 1024 + row * 256 + blk * 32 + u];
    }

    uint32_t mbar_a = s2u(mbars);
    uint32_t hb0_a  = s2u(hb0);
    uint32_t hb1_a  = s2u(hb1);
    uint32_t hst_a  = s2u(hstage);
    if (tid == 0) {
        asm volatile("mbarrier.init.shared.b64 [%0], %1;" :: "r"(mbar_a),     "r"(1) : "memory");
        asm volatile("mbarrier.init.shared.b64 [%0], %1;" :: "r"(mbar_a + 8), "r"(1) : "memory");
        asm volatile("mbarrier.arrive.expect_tx.shared.b64 _, [%0], %1;"
                     :: "r"(mbar_a), "r"(4096) : "memory");
        asm volatile("mbarrier.arrive.expect_tx.shared.b64 _, [%0], %1;"
                     :: "r"(mbar_a + 8), "r"(4096) : "memory");
    }
    __syncthreads();
    asm volatile("barrier.cluster.arrive.aligned;" ::: "memory");
    asm volatile("barrier.cluster.wait.aligned;"   ::: "memory");

    int erow = tid >> 5, eul = tid & 31;      // elementwise role (tid < 128)
    int egu  = cslot * 32 + eul;              // global unit index
    float c_st = 0.f, wc0 = 0.f, wc1 = 0.f, wc2 = 0.f;
    if (tid < 128) {
        c_st = c0[(grp * 4 + erow) * 256 + egu];
        wc0 = Wc[egu]; wc1 = Wc[256 + egu]; wc2 = Wc[512 + egu];
    }

    unsigned par0 = 0, par1 = 0;
    for (int t = 0; t < 4096; t++) {
        int p = t & 1;
        const float* hb = p ? hb1 : hb0;

        // prefetch xw (+bias baked in, 4 gates) and j (hides under wait+GEMV)
        float xw0 = 0.f, xw1 = 0.f, xw2 = 0.f, xw3 = 0.f, jv = 0.f;
        if (tid < 128) {
            size_t xb = ((size_t)(grp * 4 + erow) * 4096 + t) * 1024 + egu;
            xw0 = __ldg(g_xw + xb);
            xw1 = __ldg(g_xw + xb + 256);
            xw2 = __ldg(g_xw + xb + 512);
            xw3 = __ldg(g_xw + xb + 768);
            jv  = __ldg(g_j + ((size_t)(grp * 4 + erow) * 4096 + t) * 256 + egu);
        }

        // wait for this step's h buffer (skip t=0: preloaded)
        if (t > 0) {
            uint32_t mb = mbar_a + (p ? 8u : 0u);
            unsigned par = p ? par1 : par0;
            asm volatile(
                "{\n\t.reg .pred P;\n\t"
                "WL%=:\n\t"
                "mbarrier.try_wait.parity.acquire.cta.shared::cta.b64 P, [%0], %1, 0x989680;\n\t"
                "@P bra WD%=;\n\t"
                "bra WL%=;\n\t"
                "WD%=:\n\t}"
                :: "r"(mb), "r"(par) : "memory");
            if (p) par1 ^= 1; else par0 ^= 1;
            if (tid == 0)   // re-arm for next phase of this barrier
                asm volatile("mbarrier.arrive.expect_tx.shared.b64 _, [%0], %1;"
                             :: "r"(mb), "r"(4096) : "memory");
        }

        // GEMV quarter: packed f32x2, weights in regs, h broadcast from smem
        ull acc0 = 0ull, acc1 = 0ull, acc2v = 0ull, acc3v = 0ull;
        #pragma unroll
        for (int b = 0; b < 2; b++) {
            const float* base = hb + (kh * 2 + b) * 128;
            #pragma unroll
            for (int u = 0; u < 32; u += 2) {
                ull w  = w2[b * 16 + (u >> 1)];
                ull h0v = *(const ull*)(base + u);
                ull h1v = *(const ull*)(base + 32 + u);
                ull h2v = *(const ull*)(base + 64 + u);
                ull h3v = *(const ull*)(base + 96 + u);
                FMA2(acc0, h0v, w);
                FMA2(acc1, h1v, w);
                FMA2(acc2v, h2v, w);
                FMA2(acc3v, h3v, w);
            }
        }
        {
            float lo, hi, a0, a1, a2, a3;
            asm("mov.b64 {%0, %1}, %2;" : "=f"(lo), "=f"(hi) : "l"(acc0));  a0 = lo + hi;
            asm("mov.b64 {%0, %1}, %2;" : "=f"(lo), "=f"(hi) : "l"(acc1));  a1 = lo + hi;
            asm("mov.b64 {%0, %1}, %2;" : "=f"(lo), "=f"(hi) : "l"(acc2v)); a2 = lo + hi;
            asm("mov.b64 {%0, %1}, %2;" : "=f"(lo), "=f"(hi) : "l"(acc3v)); a3 = lo + hi;
            *(float4*)&pb[(kh * 128 + col) * 4] = make_float4(a0, a1, a2, a3);
        }
        __syncthreads();

        // elementwise LSTM update (threads 0..127), stage h(t+1) locally
        if (tid < 128) {
            float G0 = xw0, G1 = xw1, G2 = xw2, G3 = xw3;
            #pragma unroll
            for (int q = 0; q < 4; q++) {
                G0 += pb[(q * 128 + 0 * 32 + eul) * 4 + erow];
                G1 += pb[(q * 128 + 1 * 32 + eul) * 4 + erow];
                G2 += pb[(q * 128 + 2 * 32 + eul) * 4 + erow];
                G3 += pb[(q * 128 + 3 * 32 + eul) * 4 + erow];
            }
            float cc = c_st;
            float iv = sigf(G0 + cc * wc0);
            float fv = sigf(G1 + cc * wc1);
            float gv = tanhfast(G2);
            float ov = sigf(G3 + cc * wc2);
            float chat = fv * cc + iv * gv;
            float cn = jv * chat + (1.f - jv) * cc;
            float hh = ov * tanhfast(chat);
            float hprev = hb[cslot * 128 + erow * 32 + eul];
            float hn = jv * hh + (1.f - jv) * hprev;
            c_st = cn;
            if (t < 4095)
                hstage[(1 - p) * 128 + tid] = hn;
            else
                g_h[(grp * 4 + erow) * 256 + egu] = hn;
        }
        __syncthreads();

        // threads 0..7 each push the CTA's 512B chunk to one peer CTA
        if (t < 4095 && tid < 8) {
            asm volatile("fence.proxy.async.shared::cta;" ::: "memory");
            uint32_t src  = hst_a + (uint32_t)((1 - p) * 512);
            uint32_t dstl = (p ? hb0_a : hb1_a) + (uint32_t)(cslot * 512);
            uint32_t mbl  = mbar_a + (p ? 0u : 8u);   // barrier of buffer 1-p
            uint32_t dst, mbr;
            asm("mapa.shared::cluster.u32 %0, %1, %2;" : "=r"(dst) : "r"(dstl), "r"(tid));
            asm("mapa.shared::cluster.u32 %0, %1, %2;" : "=r"(mbr) : "r"(mbl),  "r"(tid));
            asm volatile(
                "cp.async.bulk.shared::cluster.shared::cta.mbarrier::complete_tx::bytes "
                "[%0], [%1], %2, [%3];"
                :: "r"(dst), "r"(src), "r"(512), "r"(mbr) : "memory");
        }
    }

    asm volatile("barrier.cluster.arrive.aligned;" ::: "memory");
    asm volatile("barrier.cluster.wait.aligned;"   ::: "memory");
}

// ---------------- final: out = h_T @ Wlin + blin ----------------
__global__ void k_final(const float* __restrict__ Wlin,
                        const float* __restrict__ blin, float* __restrict__ out) {
    __shared__ float hsm[256];
    int b = blockIdx.x, d = threadIdx.x;   // 64 threads
    for (int i = d; i < 256; i += 64) hsm[i] = g_h[b * 256 + i];
    __syncthreads();
    float acc = blin[d];
    #pragma unroll 8
    for (int k = 0; k < 256; k++) acc += hsm[k] * Wlin[k * 64 + d];
    out[b * 64 + d] = acc;
}

// ---------------- launcher ----------------
extern "C" void kernel_launch(void* const* d_in, const int* in_sizes, int n_in,
                              void* d_out, int out_size) {
    (void)in_sizes; (void)n_in; (void)out_size;
    const float* ev   = (const float*)d_in[0];
    const float* vc   = (const float*)d_in[2];
    const float* vn   = (const float*)d_in[3];
    const float* h0   = (const float*)d_in[4];
    const float* c0   = (const float*)d_in[5];
    const float* Wx   = (const float*)d_in[6];
    const float* Wh   = (const float*)d_in[7];
    const float* Wc   = (const float*)d_in[8];
    const float* bias = (const float*)d_in[9];
    const float* Ve   = (const float*)d_in[10];
    const float* Vc   = (const float*)d_in[11];
    const float* Vn   = (const float*)d_in[12];
    const float* Wlin = (const float*)d_in[13];
    const float* blin = (const float*)d_in[14];
    const float* Wef1 = (const float*)d_in[15];
    const float* bef1 = (const float*)d_in[16];
    const float* Wef3 = (const float*)d_in[17];
    const float* bef3 = (const float*)d_in[18];
    float* out = (float*)d_out;

    cudaFuncSetAttribute(k_embed, cudaFuncAttributeMaxDynamicSharedMemorySize, 71680);
    cudaFuncSetAttribute(k_gemm,  cudaFuncAttributeMaxDynamicSharedMemorySize, 65536);

    void *ps, *px, *pu, *pxw, *pj;
    cudaGetSymbolAddress(&ps,  g_s);
    cudaGetSymbolAddress(&px,  g_x);
    cudaGetSymbolAddress(&pu,  g_u);
    cudaGetSymbolAddress(&pxw, g_xw);
    cudaGetSymbolAddress(&pj,  g_j);

    k_embed<<<MROWS / 32, 256, 71680>>>(ev, vc, vn, Ve, Vc, Vn);
    // xW = x @ Wx + bias            [M,1024]
    k_gemm<<<dim3(MROWS / 64, 16), 256, 65536>>>((const float*)px, Wx, bias,
                                                 (float*)pxw, 1024, 0);
    // u = tanh(s @ Wef1 + bef1)     [M,128]
    k_gemm<<<dim3(MROWS / 64, 2), 256, 65536>>>((const float*)ps, Wef1, bef1,
                                                (float*)pu, 128, 1);
    // j = sigmoid(u @ Wef3 + bef3)  [M,256]
    k_gemm<<<dim3(MROWS / 64, 4), 256, 65536>>>((const float*)pu, Wef3, bef3,
                                                (float*)pj, 256, 2);
    k_recur<<<128, 512>>>(h0, c0, Wh, Wc);
    k_final<<<64, 64>>>(Wlin, blin, out);
}

// round 7
// speedup vs baseline: 2.2636x; 1.0155x over previous
#include <cuda_runtime.h>
#include <cuda_bf16.h>
#include <cstdint>
#include <math.h>

#define S_LEN 4096
#define BATCH 64
#define HSZ   256
#define MROWS (BATCH * S_LEN)   // 262144

typedef unsigned long long ull;

// ---------------- device scratch (allocation-free rule) ----------------
__device__ float g_x [(size_t)MROWS * 128];           // x
__device__ float g_u [(size_t)MROWS * 128];           // tanh(s@Wef1+bef1)
__device__ float g_xw[(size_t)MROWS * 1024];          // [b][s][4HS] (bias baked in)
__device__ float g_j [(size_t)MROWS * HSZ];           // [b][s][HS]
__device__ float g_h [BATCH * HSZ];                   // final h

// fast activations: MUFU-based, saturate correctly at +-inf
__device__ __forceinline__ float sigf(float x) {
    return __fdividef(1.0f, 1.0f + __expf(-x));
}
__device__ __forceinline__ float tanhfast(float x) {
    return 1.0f - __fdividef(2.0f, __expf(2.0f * x) + 1.0f);
}

__device__ __forceinline__ uint32_t s2u(const void* p) {
    uint32_t r;
    asm("{ .reg .u64 t; cvta.to.shared.u64 t, %1; cvt.u32.u64 %0, t; }"
        : "=r"(r) : "l"(p));
    return r;
}

#define FMA2(d, a, b) \
    asm("fma.rn.f32x2 %0, %1, %2, %0;" : "+l"(d) : "l"(a), "l"(b))
#define PACK2(d, a) \
    asm("mov.b64 %0, {%1, %1};" : "=l"(d) : "f"(a))

// ---------------- fused embeddings + event-filter stage 1 ------------------
// s = ev@Ve ; x = s + 2*(vc@Vc + tanh(vn@Vn)) ; u = tanh(s@Wef1 + bef1)
// tile: 32 rows, 256 threads, thread = 2 rows x 8 cols
__global__ void __launch_bounds__(256, 1)
k_embed_u(const float* __restrict__ ev, const float* __restrict__ vc,
          const float* __restrict__ vn, const float* __restrict__ Ve,
          const float* __restrict__ Vc, const float* __restrict__ Vn,
          const float* __restrict__ Wef1, const float* __restrict__ bef1) {
    extern __shared__ float sm[];
    float* wE  = sm;                 // [64][128] (floats 0..8191)   -> Wef1 later
    float* wC  = sm + 8192;          // [32][128]
    float* wN  = sm + 12288;         // [16][128]
    float* ie  = sm + 16384;         // [32][64]
    float* ic  = ie + 2048;          // [32][32]
    float* inn = ic + 1024;          // [32][16]
    float* st  = sm + 19968;         // s-tile [32][128]
    int tid = threadIdx.x;
    size_t rb = (size_t)blockIdx.x * 32;

    for (int i = tid; i < 2048; i += 256) ((float4*)wE)[i]  = ((const float4*)Ve)[i];
    for (int i = tid; i < 1024; i += 256) ((float4*)wC)[i]  = ((const float4*)Vc)[i];
    for (int i = tid; i < 512;  i += 256) ((float4*)wN)[i]  = ((const float4*)Vn)[i];
    for (int i = tid; i < 512;  i += 256) ((float4*)ie)[i]  = ((const float4*)(ev + rb * 64))[i];
    for (int i = tid; i < 256;  i += 256) ((float4*)ic)[i]  = ((const float4*)(vc + rb * 32))[i];
    for (int i = tid; i < 128;  i += 256) ((float4*)inn)[i] = ((const float4*)(vn + rb * 16))[i];
    __syncthreads();

    int ty = tid >> 4, tx = tid & 15;   // rows ty*2+{0,1}, cols tx*8+{0..7}
    float sa[2][8], ta[2][8], xa[2][8];
    #pragma unroll
    for (int r = 0; r < 2; r++)
        #pragma unroll
        for (int j = 0; j < 8; j++) { sa[r][j] = 0.f; ta[r][j] = 0.f; }

    #pragma unroll 4
    for (int k = 0; k < 64; k++) {
        float a0 = ie[(ty * 2) * 64 + k], a1 = ie[(ty * 2 + 1) * 64 + k];
        const float* wr = wE + k * 128 + tx * 8;
        float4 w0 = *(const float4*)wr, w1 = *(const float4*)(wr + 4);
        float w[8] = {w0.x, w0.y, w0.z, w0.w, w1.x, w1.y, w1.z, w1.w};
        #pragma unroll
        for (int j = 0; j < 8; j++) { sa[0][j] += a0 * w[j]; sa[1][j] += a1 * w[j]; }
    }
    #pragma unroll 4
    for (int k = 0; k < 32; k++) {
        float a0 = ic[(ty * 2) * 32 + k], a1 = ic[(ty * 2 + 1) * 32 + k];
        const float* wr = wC + k * 128 + tx * 8;
        float4 w0 = *(const float4*)wr, w1 = *(const float4*)(wr + 4);
        float w[8] = {w0.x, w0.y, w0.z, w0.w, w1.x, w1.y, w1.z, w1.w};
        #pragma unroll
        for (int j = 0; j < 8; j++) { ta[0][j] += a0 * w[j]; ta[1][j] += a1 * w[j]; }
    }
    #pragma unroll
    for (int r = 0; r < 2; r++)
        #pragma unroll
        for (int j = 0; j < 8; j++) { xa[r][j] = 2.f * ta[r][j]; ta[r][j] = 0.f; }
    #pragma unroll 4
    for (int k = 0; k < 16; k++) {
        float a0 = inn[(ty * 2) * 16 + k], a1 = inn[(ty * 2 + 1) * 16 + k];
        const float* wr = wN + k * 128 + tx * 8;
        float4 w0 = *(const float4*)wr, w1 = *(const float4*)(wr + 4);
        float w[8] = {w0.x, w0.y, w0.z, w0.w, w1.x, w1.y, w1.z, w1.w};
        #pragma unroll
        for (int j = 0; j < 8; j++) { ta[0][j] += a0 * w[j]; ta[1][j] += a1 * w[j]; }
    }
    // write x to gmem; stash s into smem tile
    #pragma unroll
    for (int r = 0; r < 2; r++) {
        int row = ty * 2 + r;
        size_t grow = rb + row;
        float o[8];
        #pragma unroll
        for (int j = 0; j < 8; j++) o[j] = sa[r][j] + xa[r][j] + 2.f * tanhfast(ta[r][j]);
        float* xp = g_x + grow * 128 + tx * 8;
        *(float4*)xp       = make_float4(o[0], o[1], o[2], o[3]);
        *(float4*)(xp + 4) = make_float4(o[4], o[5], o[6], o[7]);
        float* sp = st + row * 128 + tx * 8;
        *(float4*)sp       = make_float4(sa[r][0], sa[r][1], sa[r][2], sa[r][3]);
        *(float4*)(sp + 4) = make_float4(sa[r][4], sa[r][5], sa[r][6], sa[r][7]);
    }
    __syncthreads();

    // overlay Wef1 [128][128] onto the weight region
    for (int i = tid; i < 4096; i += 256) ((float4*)wE)[i] = ((const float4*)Wef1)[i];
    __syncthreads();

    // u = tanh(s @ Wef1 + bef1)
    float ua[2][8];
    #pragma unroll
    for (int r = 0; r < 2; r++)
        #pragma unroll
        for (int j = 0; j < 8; j++) ua[r][j] = 0.f;
    #pragma unroll 4
    for (int k = 0; k < 128; k++) {
        float a0 = st[(ty * 2) * 128 + k], a1 = st[(ty * 2 + 1) * 128 + k];
        const float* wr = wE + k * 128 + tx * 8;
        float4 w0 = *(const float4*)wr, w1 = *(const float4*)(wr + 4);
        float w[8] = {w0.x, w0.y, w0.z, w0.w, w1.x, w1.y, w1.z, w1.w};
        #pragma unroll
        for (int j = 0; j < 8; j++) { ua[0][j] += a0 * w[j]; ua[1][j] += a1 * w[j]; }
    }
    float4 b0 = *(const float4*)&bef1[tx * 8];
    float4 b1 = *(const float4*)&bef1[tx * 8 + 4];
    float bb[8] = {b0.x, b0.y, b0.z, b0.w, b1.x, b1.y, b1.z, b1.w};
    #pragma unroll
    for (int r = 0; r < 2; r++) {
        size_t grow = rb + ty * 2 + r;
        float o[8];
        #pragma unroll
        for (int j = 0; j < 8; j++) o[j] = tanhfast(ua[r][j] + bb[j]);
        float* up = g_u + grow * 128 + tx * 8;
        *(float4*)up       = make_float4(o[0], o[1], o[2], o[3]);
        *(float4*)(up + 4) = make_float4(o[4], o[5], o[6], o[7]);
    }
}

// ---------------- generic K=128 GEMM (f32x2): out = act(A@W + bias) --------
__global__ void __launch_bounds__(256)
k_gemm(const float* __restrict__ A, const float* __restrict__ W,
       const float* __restrict__ bias, float* __restrict__ out,
       int N, int act) {
    extern __shared__ float sm[];
    float* As = sm;            // [64][128]
    float* Ws = sm + 64 * 128; // [128][64]
    int tid = threadIdx.x;
    const float4* A4 = (const float4*)A;
    const float4* W4 = (const float4*)W;
    for (int i = tid; i < 2048; i += 256)
        ((float4*)As)[i] = A4[((size_t)blockIdx.x * 64 + (i >> 5)) * 32 + (i & 31)];
    for (int i = tid; i < 2048; i += 256)
        ((float4*)Ws)[i] = W4[(size_t)(i >> 4) * (N >> 2) + blockIdx.y * 16 + (i & 15)];
    __syncthreads();

    int ty = tid >> 4, tx = tid & 15;
    int r0 = ty * 4, c0 = tx * 4;
    ull acc[4][2];
    #pragma unroll
    for (int r = 0; r < 4; r++) { acc[r][0] = 0ull; acc[r][1] = 0ull; }

    #pragma unroll 4
    for (int kk = 0; kk < 128; kk += 4) {
        float4 av[4];
        ulonglong2 wv[4];
        #pragma unroll
        for (int r = 0; r < 4; r++) av[r] = *(const float4*)&As[(r0 + r) * 128 + kk];
        #pragma unroll
        for (int i = 0; i < 4; i++) wv[i] = *(const ulonglong2*)&Ws[(kk + i) * 64 + c0];
        #pragma unroll
        for (int r = 0; r < 4; r++) {
            ull ad;
            PACK2(ad, av[r].x); FMA2(acc[r][0], ad, wv[0].x); FMA2(acc[r][1], ad, wv[0].y);
            PACK2(ad, av[r].y); FMA2(acc[r][0], ad, wv[1].x); FMA2(acc[r][1], ad, wv[1].y);
            PACK2(ad, av[r].z); FMA2(acc[r][0], ad, wv[2].x); FMA2(acc[r][1], ad, wv[2].y);
            PACK2(ad, av[r].w); FMA2(acc[r][0], ad, wv[3].x); FMA2(acc[r][1], ad, wv[3].y);
        }
    }

    int colg = blockIdx.y * 64 + c0;
    float4 bv = *(const float4*)&bias[colg];
    #pragma unroll
    for (int r = 0; r < 4; r++) {
        size_t rg = (size_t)blockIdx.x * 64 + r0 + r;
        float v[4];
        asm("mov.b64 {%0, %1}, %2;" : "=f"(v[0]), "=f"(v[1]) : "l"(acc[r][0]));
        asm("mov.b64 {%0, %1}, %2;" : "=f"(v[2]), "=f"(v[3]) : "l"(acc[r][1]));
        v[0] += bv.x; v[1] += bv.y; v[2] += bv.z; v[3] += bv.w;
        if (act == 1) {
            #pragma unroll
            for (int c = 0; c < 4; c++) v[c] = tanhfast(v[c]);
        } else if (act == 2) {
            #pragma unroll
            for (int c = 0; c < 4; c++) v[c] = sigf(v[c]);
        }
        *(float4*)&out[rg * N + colg] = make_float4(v[0], v[1], v[2], v[3]);
    }
}

// ---------------- recurrence: 16 clusters of 8 CTAs, 512 threads ----------
// cluster g owns batch rows 4g..4g+3; rank c owns units 32c..32c+31 (4 gates)
// h buffers [block(8)][row(4)][unit(32)]: each CTA's contribution is one
// contiguous 512B chunk -> ONE bulk DSMEM copy per peer per step.
// Barriers: GEMV-only warps bar.arrive; elementwise warps bar.sync.
__global__ void __launch_bounds__(512, 1) __cluster_dims__(8, 1, 1)
k_recur(const float* __restrict__ h0, const float* __restrict__ c0,
        const float* __restrict__ Wh, const float* __restrict__ Wc) {
    __shared__ float hb0[1024];      // h buffer 0  [blk][row][32]
    __shared__ float hb1[1024];      // h buffer 1
    __shared__ float pb[2048];       // [row(4)][kh(4)][col(128)]  conflict-free
    __shared__ float hstage[256];    // [phase(2)][row(4)][unit(32)]
    __shared__ ull   mbars[2];

    int tid   = threadIdx.x;
    int grp   = blockIdx.x >> 3;
    int cslot = blockIdx.x & 7;

    int col = tid & 127, kh = tid >> 7;       // kh in 0..3: K-quarter
    int gq = col >> 5, gul = col & 31;
    int gcol = gq * 256 + cslot * 32 + gul;   // global gate column

    // Wh slice in registers: 32 f32x2 pairs covering K-quarter kh
    ull w2[32];
    {
        const float* whp = Wh + gcol;
        #pragma unroll
        for (int i = 0; i < 32; i++) {
            int k = kh * 64 + 2 * i;
            float wlo = __ldg(whp + (size_t)k * 1024);
            float whi = __ldg(whp + (size_t)(k + 1) * 1024);
            asm("mov.b64 %0, {%1, %2};" : "=l"(w2[i]) : "f"(wlo), "f"(whi));
        }
    }

    // h(0) into buffer 0, [blk][row][32] layout
    for (int i = tid; i < 1024; i += 512) {
        int blk = i >> 7, row = (i >> 5) & 3, u = i & 31;
        hb0[i] = h0[grp * 1024 + row * 256 + blk * 32 + u];
    }

    uint32_t mbar_a = s2u(mbars);
    uint32_t hb0_a  = s2u(hb0);
    uint32_t hb1_a  = s2u(hb1);
    uint32_t hst_a  = s2u(hstage);
    if (tid == 0) {
        asm volatile("mbarrier.init.shared.b64 [%0], %1;" :: "r"(mbar_a),     "r"(1) : "memory");
        asm volatile("mbarrier.init.shared.b64 [%0], %1;" :: "r"(mbar_a + 8), "r"(1) : "memory");
        asm volatile("mbarrier.arrive.expect_tx.shared.b64 _, [%0], %1;"
                     :: "r"(mbar_a), "r"(4096) : "memory");
        asm volatile("mbarrier.arrive.expect_tx.shared.b64 _, [%0], %1;"
                     :: "r"(mbar_a + 8), "r"(4096) : "memory");
    }
    __syncthreads();
    asm volatile("barrier.cluster.arrive.aligned;" ::: "memory");
    asm volatile("barrier.cluster.wait.aligned;"   ::: "memory");

    int erow = tid >> 5, eul = tid & 31;      // elementwise role (tid < 128)
    int egu  = cslot * 32 + eul;              // global unit index
    float c_st = 0.f, wc0 = 0.f, wc1 = 0.f, wc2 = 0.f;
    if (tid < 128) {
        c_st = c0[(grp * 4 + erow) * 256 + egu];
        wc0 = Wc[egu]; wc1 = Wc[256 + egu]; wc2 = Wc[512 + egu];
    }

    unsigned par0 = 0, par1 = 0;
    for (int t = 0; t < 4096; t++) {
        int p = t & 1;
        const float* hb = p ? hb1 : hb0;

        // prefetch xw (+bias baked in, 4 gates) and j (hides under wait+GEMV)
        float xw0 = 0.f, xw1 = 0.f, xw2 = 0.f, xw3 = 0.f, jv = 0.f;
        if (tid < 128) {
            size_t xb = ((size_t)(grp * 4 + erow) * 4096 + t) * 1024 + egu;
            xw0 = __ldg(g_xw + xb);
            xw1 = __ldg(g_xw + xb + 256);
            xw2 = __ldg(g_xw + xb + 512);
            xw3 = __ldg(g_xw + xb + 768);
            jv  = __ldg(g_j + ((size_t)(grp * 4 + erow) * 4096 + t) * 256 + egu);
        }

        // wait for this step's h buffer (skip t=0: preloaded)
        if (t > 0) {
            uint32_t mb = mbar_a + (p ? 8u : 0u);
            unsigned par = p ? par1 : par0;
            asm volatile(
                "{\n\t.reg .pred P;\n\t"
                "WL%=:\n\t"
                "mbarrier.try_wait.parity.acquire.cta.shared::cta.b64 P, [%0], %1, 0x989680;\n\t"
                "@P bra WD%=;\n\t"
                "bra WL%=;\n\t"
                "WD%=:\n\t}"
                :: "r"(mb), "r"(par) : "memory");
            if (p) par1 ^= 1; else par0 ^= 1;
            if (tid == 0)   // re-arm for this barrier's next phase (step t+2)
                asm volatile("mbarrier.arrive.expect_tx.shared.b64 _, [%0], %1;"
                             :: "r"(mb), "r"(4096) : "memory");
        }

        // GEMV quarter: packed f32x2, weights in regs, h broadcast from smem
        ull acc0 = 0ull, acc1 = 0ull, acc2v = 0ull, acc3v = 0ull;
        #pragma unroll
        for (int b = 0; b < 2; b++) {
            const float* base = hb + (kh * 2 + b) * 128;
            #pragma unroll
            for (int u = 0; u < 32; u += 2) {
                ull w  = w2[b * 16 + (u >> 1)];
                ull h0v = *(const ull*)(base + u);
                ull h1v = *(const ull*)(base + 32 + u);
                ull h2v = *(const ull*)(base + 64 + u);
                ull h3v = *(const ull*)(base + 96 + u);
                FMA2(acc0, h0v, w);
                FMA2(acc1, h1v, w);
                FMA2(acc2v, h2v, w);
                FMA2(acc3v, h3v, w);
            }
        }
        {
            float lo, hi;
            asm("mov.b64 {%0, %1}, %2;" : "=f"(lo), "=f"(hi) : "l"(acc0));
            pb[0 * 512 + kh * 128 + col] = lo + hi;
            asm("mov.b64 {%0, %1}, %2;" : "=f"(lo), "=f"(hi) : "l"(acc1));
            pb[1 * 512 + kh * 128 + col] = lo + hi;
            asm("mov.b64 {%0, %1}, %2;" : "=f"(lo), "=f"(hi) : "l"(acc2v));
            pb[2 * 512 + kh * 128 + col] = lo + hi;
            asm("mov.b64 {%0, %1}, %2;" : "=f"(lo), "=f"(hi) : "l"(acc3v));
            pb[3 * 512 + kh * 128 + col] = lo + hi;
        }

        if (tid >= 128) {
            // GEMV-only warps: post arrival, head straight to next wait
            asm volatile("bar.arrive 0, 512;" ::: "memory");
        } else {
            asm volatile("bar.sync 0, 512;" ::: "memory");
            // elementwise LSTM update (threads 0..127)
            const float* pr = pb + erow * 512;
            float G0 = xw0, G1 = xw1, G2 = xw2, G3 = xw3;
            #pragma unroll
            for (int q = 0; q < 4; q++) {
                G0 += pr[q * 128 +   0 + eul];
                G1 += pr[q * 128 +  32 + eul];
                G2 += pr[q * 128 +  64 + eul];
                G3 += pr[q * 128 +  96 + eul];
            }
            float cc = c_st;
            float iv = sigf(G0 + cc * wc0);
            float fv = sigf(G1 + cc * wc1);
            float gv = tanhfast(G2);
            float ov = sigf(G3 + cc * wc2);
            float chat = fv * cc + iv * gv;
            float cn = jv * chat + (1.f - jv) * cc;
            float hh = ov * tanhfast(chat);
            float hprev = hb[cslot * 128 + erow * 32 + eul];
            float hn = jv * hh + (1.f - jv) * hprev;
            c_st = cn;
            if (t < 4095)
                hstage[(1 - p) * 128 + tid] = hn;
            else
                g_h[(grp * 4 + erow) * 256 + egu] = hn;
            asm volatile("bar.sync 1, 128;" ::: "memory");
            // threads 0..7 each push the CTA's 512B chunk to one peer CTA
            if (t < 4095 && tid < 8) {
                asm volatile("fence.proxy.async.shared::cta;" ::: "memory");
                uint32_t src  = hst_a + (uint32_t)((1 - p) * 512);
                uint32_t dstl = (p ? hb0_a : hb1_a) + (uint32_t)(cslot * 512);
                uint32_t mbl  = mbar_a + (p ? 0u : 8u);   // barrier of buffer 1-p
                uint32_t dst, mbr;
                asm("mapa.shared::cluster.u32 %0, %1, %2;" : "=r"(dst) : "r"(dstl), "r"(tid));
                asm("mapa.shared::cluster.u32 %0, %1, %2;" : "=r"(mbr) : "r"(mbl),  "r"(tid));
                asm volatile(
                    "cp.async.bulk.shared::cluster.shared::cta.mbarrier::complete_tx::bytes "
                    "[%0], [%1], %2, [%3];"
                    :: "r"(dst), "r"(src), "r"(512), "r"(mbr) : "memory");
            }
        }
    }

    asm volatile("barrier.cluster.arrive.aligned;" ::: "memory");
    asm volatile("barrier.cluster.wait.aligned;"   ::: "memory");
}

// ---------------- final: out = h_T @ Wlin + blin ----------------
__global__ void k_final(const float* __restrict__ Wlin,
                        const float* __restrict__ blin, float* __restrict__ out) {
    __shared__ float hsm[256];
    int b = blockIdx.x, d = threadIdx.x;   // 64 threads
    for (int i = d; i < 256; i += 64) hsm[i] = g_h[b * 256 + i];
    __syncthreads();
    float acc = blin[d];
    #pragma unroll 8
    for (int k = 0; k < 256; k++) acc += hsm[k] * Wlin[k * 64 + d];
    out[b * 64 + d] = acc;
}

// ---------------- launcher ----------------
extern "C" void kernel_launch(void* const* d_in, const int* in_sizes, int n_in,
                              void* d_out, int out_size) {
    (void)in_sizes; (void)n_in; (void)out_size;
    const float* ev   = (const float*)d_in[0];
    const float* vc   = (const float*)d_in[2];
    const float* vn   = (const float*)d_in[3];
    const float* h0   = (const float*)d_in[4];
    const float* c0   = (const float*)d_in[5];
    const float* Wx   = (const float*)d_in[6];
    const float* Wh   = (const float*)d_in[7];
    const float* Wc   = (const float*)d_in[8];
    const float* bias = (const float*)d_in[9];
    const float* Ve   = (const float*)d_in[10];
    const float* Vc   = (const float*)d_in[11];
    const float* Vn   = (const float*)d_in[12];
    const float* Wlin = (const float*)d_in[13];
    const float* blin = (const float*)d_in[14];
    const float* Wef1 = (const float*)d_in[15];
    const float* bef1 = (const float*)d_in[16];
    const float* Wef3 = (const float*)d_in[17];
    const float* bef3 = (const float*)d_in[18];
    float* out = (float*)d_out;

    cudaFuncSetAttribute(k_embed_u, cudaFuncAttributeMaxDynamicSharedMemorySize, 96256);
    cudaFuncSetAttribute(k_gemm,    cudaFuncAttributeMaxDynamicSharedMemorySize, 65536);

    void *px, *pu, *pxw, *pj;
    cudaGetSymbolAddress(&px,  g_x);
    cudaGetSymbolAddress(&pu,  g_u);
    cudaGetSymbolAddress(&pxw, g_xw);
    cudaGetSymbolAddress(&pj,  g_j);

    // 1: embeddings + u (fused)
    k_embed_u<<<MROWS / 32, 256, 96256>>>(ev, vc, vn, Ve, Vc, Vn, Wef1, bef1);
    // 2: xW = x @ Wx + bias            [M,1024]
    k_gemm<<<dim3(MROWS / 64, 16), 256, 65536>>>((const float*)px, Wx, bias,
                                                 (float*)pxw, 1024, 0);
    // 3: j = sigmoid(u @ Wef3 + bef3)  [M,256]
    k_gemm<<<dim3(MROWS / 64, 4), 256, 65536>>>((const float*)pu, Wef3, bef3,
                                                (float*)pj, 256, 2);
    // 4: recurrence (target of ncu capture)
    k_recur<<<128, 512>>>(h0, c0, Wh, Wc);
    // 5: output projection
    k_final<<<64, 64>>>(Wlin, blin, out);
}

// round 8
// speedup vs baseline: 2.5436x; 1.1237x over previous
#include <cuda_runtime.h>
#include <cuda_bf16.h>
#include <cstdint>
#include <math.h>

#define S_LEN 4096
#define BATCH 64
#define HSZ   256
#define MROWS (BATCH * S_LEN)   // 262144

typedef unsigned long long ull;

// ---------------- device scratch (allocation-free rule) ----------------
__device__ float g_x [(size_t)MROWS * 128];           // x
__device__ float g_u [(size_t)MROWS * 128];           // tanh(s@Wef1+bef1)
__device__ float g_xw[(size_t)MROWS * 1024];          // [b][s][4HS] (bias baked in)
__device__ float g_j [(size_t)MROWS * HSZ];           // [b][s][HS]
__device__ float g_h [BATCH * HSZ];                   // final h

// fast activations: MUFU-based, saturate correctly at +-inf
__device__ __forceinline__ float sigf(float x) {
    return __fdividef(1.0f, 1.0f + __expf(-x));
}
__device__ __forceinline__ float tanhfast(float x) {
    return 1.0f - __fdividef(2.0f, __expf(2.0f * x) + 1.0f);
}

__device__ __forceinline__ uint32_t s2u(const void* p) {
    uint32_t r;
    asm("{ .reg .u64 t; cvta.to.shared.u64 t, %1; cvt.u32.u64 %0, t; }"
        : "=r"(r) : "l"(p));
    return r;
}

#define FMA2(d, a, b) \
    asm("fma.rn.f32x2 %0, %1, %2, %0;" : "+l"(d) : "l"(a), "l"(b))
#define PACK2(d, a) \
    asm("mov.b64 %0, {%1, %1};" : "=l"(d) : "f"(a))

// ---------------- fused embeddings + event-filter stage 1 ------------------
// s = ev@Ve ; x = s + 2*(vc@Vc + tanh(vn@Vn)) ; u = tanh(s@Wef1 + bef1)
// tile: 32 rows, 256 threads, thread = 2 rows x 8 cols
__global__ void __launch_bounds__(256, 1)
k_embed_u(const float* __restrict__ ev, const float* __restrict__ vc,
          const float* __restrict__ vn, const float* __restrict__ Ve,
          const float* __restrict__ Vc, const float* __restrict__ Vn,
          const float* __restrict__ Wef1, const float* __restrict__ bef1) {
    extern __shared__ float sm[];
    float* wE  = sm;                 // [64][128] (floats 0..8191)   -> Wef1 later
    float* wC  = sm + 8192;          // [32][128]
    float* wN  = sm + 12288;         // [16][128]
    float* ie  = sm + 16384;         // [32][64]
    float* ic  = ie + 2048;          // [32][32]
    float* inn = ic + 1024;          // [32][16]
    float* st  = sm + 19968;         // s-tile [32][128]
    int tid = threadIdx.x;
    size_t rb = (size_t)blockIdx.x * 32;

    for (int i = tid; i < 2048; i += 256) ((float4*)wE)[i]  = ((const float4*)Ve)[i];
    for (int i = tid; i < 1024; i += 256) ((float4*)wC)[i]  = ((const float4*)Vc)[i];
    for (int i = tid; i < 512;  i += 256) ((float4*)wN)[i]  = ((const float4*)Vn)[i];
    for (int i = tid; i < 512;  i += 256) ((float4*)ie)[i]  = ((const float4*)(ev + rb * 64))[i];
    for (int i = tid; i < 256;  i += 256) ((float4*)ic)[i]  = ((const float4*)(vc + rb * 32))[i];
    for (int i = tid; i < 128;  i += 256) ((float4*)inn)[i] = ((const float4*)(vn + rb * 16))[i];
    __syncthreads();

    int ty = tid >> 4, tx = tid & 15;   // rows ty*2+{0,1}, cols tx*8+{0..7}
    float sa[2][8], ta[2][8], xa[2][8];
    #pragma unroll
    for (int r = 0; r < 2; r++)
        #pragma unroll
        for (int j = 0; j < 8; j++) { sa[r][j] = 0.f; ta[r][j] = 0.f; }

    #pragma unroll 4
    for (int k = 0; k < 64; k++) {
        float a0 = ie[(ty * 2) * 64 + k], a1 = ie[(ty * 2 + 1) * 64 + k];
        const float* wr = wE + k * 128 + tx * 8;
        float4 w0 = *(const float4*)wr, w1 = *(const float4*)(wr + 4);
        float w[8] = {w0.x, w0.y, w0.z, w0.w, w1.x, w1.y, w1.z, w1.w};
        #pragma unroll
        for (int j = 0; j < 8; j++) { sa[0][j] += a0 * w[j]; sa[1][j] += a1 * w[j]; }
    }
    #pragma unroll 4
    for (int k = 0; k < 32; k++) {
        float a0 = ic[(ty * 2) * 32 + k], a1 = ic[(ty * 2 + 1) * 32 + k];
        const float* wr = wC + k * 128 + tx * 8;
        float4 w0 = *(const float4*)wr, w1 = *(const float4*)(wr + 4);
        float w[8] = {w0.x, w0.y, w0.z, w0.w, w1.x, w1.y, w1.z, w1.w};
        #pragma unroll
        for (int j = 0; j < 8; j++) { ta[0][j] += a0 * w[j]; ta[1][j] += a1 * w[j]; }
    }
    #pragma unroll
    for (int r = 0; r < 2; r++)
        #pragma unroll
        for (int j = 0; j < 8; j++) { xa[r][j] = 2.f * ta[r][j]; ta[r][j] = 0.f; }
    #pragma unroll 4
    for (int k = 0; k < 16; k++) {
        float a0 = inn[(ty * 2) * 16 + k], a1 = inn[(ty * 2 + 1) * 16 + k];
        const float* wr = wN + k * 128 + tx * 8;
        float4 w0 = *(const float4*)wr, w1 = *(const float4*)(wr + 4);
        float w[8] = {w0.x, w0.y, w0.z, w0.w, w1.x, w1.y, w1.z, w1.w};
        #pragma unroll
        for (int j = 0; j < 8; j++) { ta[0][j] += a0 * w[j]; ta[1][j] += a1 * w[j]; }
    }
    // write x to gmem; stash s into smem tile
    #pragma unroll
    for (int r = 0; r < 2; r++) {
        int row = ty * 2 + r;
        size_t grow = rb + row;
        float o[8];
        #pragma unroll
        for (int j = 0; j < 8; j++) o[j] = sa[r][j] + xa[r][j] + 2.f * tanhfast(ta[r][j]);
        float* xp = g_x + grow * 128 + tx * 8;
        *(float4*)xp       = make_float4(o[0], o[1], o[2], o[3]);
        *(float4*)(xp + 4) = make_float4(o[4], o[5], o[6], o[7]);
        float* sp = st + row * 128 + tx * 8;
        *(float4*)sp       = make_float4(sa[r][0], sa[r][1], sa[r][2], sa[r][3]);
        *(float4*)(sp + 4) = make_float4(sa[r][4], sa[r][5], sa[r][6], sa[r][7]);
    }
    __syncthreads();

    // overlay Wef1 [128][128] onto the weight region
    for (int i = tid; i < 4096; i += 256) ((float4*)wE)[i] = ((const float4*)Wef1)[i];
    __syncthreads();

    // u = tanh(s @ Wef1 + bef1)
    float ua[2][8];
    #pragma unroll
    for (int r = 0; r < 2; r++)
        #pragma unroll
        for (int j = 0; j < 8; j++) ua[r][j] = 0.f;
    #pragma unroll 4
    for (int k = 0; k < 128; k++) {
        float a0 = st[(ty * 2) * 128 + k], a1 = st[(ty * 2 + 1) * 128 + k];
        const float* wr = wE + k * 128 + tx * 8;
        float4 w0 = *(const float4*)wr, w1 = *(const float4*)(wr + 4);
        float w[8] = {w0.x, w0.y, w0.z, w0.w, w1.x, w1.y, w1.z, w1.w};
        #pragma unroll
        for (int j = 0; j < 8; j++) { ua[0][j] += a0 * w[j]; ua[1][j] += a1 * w[j]; }
    }
    float4 b0 = *(const float4*)&bef1[tx * 8];
    float4 b1 = *(const float4*)&bef1[tx * 8 + 4];
    float bb[8] = {b0.x, b0.y, b0.z, b0.w, b1.x, b1.y, b1.z, b1.w};
    #pragma unroll
    for (int r = 0; r < 2; r++) {
        size_t grow = rb + ty * 2 + r;
        float o[8];
        #pragma unroll
        for (int j = 0; j < 8; j++) o[j] = tanhfast(ua[r][j] + bb[j]);
        float* up = g_u + grow * 128 + tx * 8;
        *(float4*)up       = make_float4(o[0], o[1], o[2], o[3]);
        *(float4*)(up + 4) = make_float4(o[4], o[5], o[6], o[7]);
    }
}

// ---------------- generic K=128 GEMM (f32x2): out = act(A@W + bias) --------
__global__ void __launch_bounds__(256)
k_gemm(const float* __restrict__ A, const float* __restrict__ W,
       const float* __restrict__ bias, float* __restrict__ out,
       int N, int act) {
    extern __shared__ float sm[];
    float* As = sm;            // [64][128]
    float* Ws = sm + 64 * 128; // [128][64]
    int tid = threadIdx.x;
    const float4* A4 = (const float4*)A;
    const float4* W4 = (const float4*)W;
    for (int i = tid; i < 2048; i += 256)
        ((float4*)As)[i] = A4[((size_t)blockIdx.x * 64 + (i >> 5)) * 32 + (i & 31)];
    for (int i = tid; i < 2048; i += 256)
        ((float4*)Ws)[i] = W4[(size_t)(i >> 4) * (N >> 2) + blockIdx.y * 16 + (i & 15)];
    __syncthreads();

    int ty = tid >> 4, tx = tid & 15;
    int r0 = ty * 4, c0 = tx * 4;
    ull acc[4][2];
    #pragma unroll
    for (int r = 0; r < 4; r++) { acc[r][0] = 0ull; acc[r][1] = 0ull; }

    #pragma unroll 4
    for (int kk = 0; kk < 128; kk += 4) {
        float4 av[4];
        ulonglong2 wv[4];
        #pragma unroll
        for (int r = 0; r < 4; r++) av[r] = *(const float4*)&As[(r0 + r) * 128 + kk];
        #pragma unroll
        for (int i = 0; i < 4; i++) wv[i] = *(const ulonglong2*)&Ws[(kk + i) * 64 + c0];
        #pragma unroll
        for (int r = 0; r < 4; r++) {
            ull ad;
            PACK2(ad, av[r].x); FMA2(acc[r][0], ad, wv[0].x); FMA2(acc[r][1], ad, wv[0].y);
            PACK2(ad, av[r].y); FMA2(acc[r][0], ad, wv[1].x); FMA2(acc[r][1], ad, wv[1].y);
            PACK2(ad, av[r].z); FMA2(acc[r][0], ad, wv[2].x); FMA2(acc[r][1], ad, wv[2].y);
            PACK2(ad, av[r].w); FMA2(acc[r][0], ad, wv[3].x); FMA2(acc[r][1], ad, wv[3].y);
        }
    }

    int colg = blockIdx.y * 64 + c0;
    float4 bv = *(const float4*)&bias[colg];
    #pragma unroll
    for (int r = 0; r < 4; r++) {
        size_t rg = (size_t)blockIdx.x * 64 + r0 + r;
        float v[4];
        asm("mov.b64 {%0, %1}, %2;" : "=f"(v[0]), "=f"(v[1]) : "l"(acc[r][0]));
        asm("mov.b64 {%0, %1}, %2;" : "=f"(v[2]), "=f"(v[3]) : "l"(acc[r][1]));
        v[0] += bv.x; v[1] += bv.y; v[2] += bv.z; v[3] += bv.w;
        if (act == 1) {
            #pragma unroll
            for (int c = 0; c < 4; c++) v[c] = tanhfast(v[c]);
        } else if (act == 2) {
            #pragma unroll
            for (int c = 0; c < 4; c++) v[c] = sigf(v[c]);
        }
        *(float4*)&out[rg * N + colg] = make_float4(v[0], v[1], v[2], v[3]);
    }
}

// ---------------- recurrence: 16 clusters of 8 CTAs, 512 threads ----------
// cluster g owns batch rows 4g..4g+3; rank c owns units 32c..32c+31 (4 gates)
// h buffers [block(8)][row(4)][unit(32)]: each CTA's contribution is one
// contiguous 512B chunk -> ONE bulk DSMEM copy per peer per step.
// GEMV mapping: thread = (K-slice ks of 32, column-pair cpair) so each
// LDS.128 h broadcast feeds 4 FMA2 (2 cols x 2 pairs): 512 LDS/step/CTA.
__global__ void __launch_bounds__(512, 1) __cluster_dims__(8, 1, 1)
k_recur(const float* __restrict__ h0, const float* __restrict__ c0,
        const float* __restrict__ Wh, const float* __restrict__ Wc) {
    __shared__ float hb0[1024];      // h buffer 0  [blk][row][32]
    __shared__ float hb1[1024];      // h buffer 1
    __shared__ float pb[4096];       // [row(4)][ks(8)][col(128)]
    __shared__ float hstage[256];    // [phase(2)][row(4)][unit(32)]
    __shared__ ull   mbars[2];

    int tid   = threadIdx.x;
    int grp   = blockIdx.x >> 3;
    int cslot = blockIdx.x & 7;

    int cpair = tid & 63;            // column pair: cols 2*cpair, 2*cpair+1
    int ks    = tid >> 6;            // K-slice: K in [ks*32, ks*32+32)
    int col0  = cpair * 2;
    int gq = col0 >> 5, gul = col0 & 31;
    int gcol = gq * 256 + cslot * 32 + gul;   // global gate column (even)

    // Wh slice in registers: 2 cols x 16 f32x2 pairs over this K-slice
    ull w2[2][16];
    #pragma unroll
    for (int c = 0; c < 2; c++) {
        const float* whp = Wh + gcol + c;
        #pragma unroll
        for (int i = 0; i < 16; i++) {
            int k = ks * 32 + 2 * i;
            float wlo = __ldg(whp + (size_t)k * 1024);
            float whi = __ldg(whp + (size_t)(k + 1) * 1024);
            asm("mov.b64 %0, {%1, %2};" : "=l"(w2[c][i]) : "f"(wlo), "f"(whi));
        }
    }

    // h(0) into buffer 0, [blk][row][32] layout
    for (int i = tid; i < 1024; i += 512) {
        int blk = i >> 7, row = (i >> 5) & 3, u = i & 31;
        hb0[i] = h0[grp * 1024 + row * 256 + blk * 32 + u];
    }

    uint32_t mbar_a = s2u(mbars);
    uint32_t hb0_a  = s2u(hb0);
    uint32_t hb1_a  = s2u(hb1);
    uint32_t hst_a  = s2u(hstage);
    if (tid == 0) {
        asm volatile("mbarrier.init.shared.b64 [%0], %1;" :: "r"(mbar_a),     "r"(1) : "memory");
        asm volatile("mbarrier.init.shared.b64 [%0], %1;" :: "r"(mbar_a + 8), "r"(1) : "memory");
        asm volatile("mbarrier.arrive.expect_tx.shared.b64 _, [%0], %1;"
                     :: "r"(mbar_a), "r"(4096) : "memory");
        asm volatile("mbarrier.arrive.expect_tx.shared.b64 _, [%0], %1;"
                     :: "r"(mbar_a + 8), "r"(4096) : "memory");
    }
    __syncthreads();
    asm volatile("barrier.cluster.arrive.aligned;" ::: "memory");
    asm volatile("barrier.cluster.wait.aligned;"   ::: "memory");

    int erow = tid >> 5, eul = tid & 31;      // elementwise role (tid < 128)
    int egu  = cslot * 32 + eul;              // global unit index
    float c_st = 0.f, wc0 = 0.f, wc1 = 0.f, wc2 = 0.f;
    if (tid < 128) {
        c_st = c0[(grp * 4 + erow) * 256 + egu];
        wc0 = Wc[egu]; wc1 = Wc[256 + egu]; wc2 = Wc[512 + egu];
    }

    unsigned par0 = 0, par1 = 0;
    for (int t = 0; t < 4096; t++) {
        int p = t & 1;
        const float* hb = p ? hb1 : hb0;

        // prefetch xw (+bias baked in, 4 gates) and j (hides under wait+GEMV)
        float xw0 = 0.f, xw1 = 0.f, xw2 = 0.f, xw3 = 0.f, jv = 0.f;
        if (tid < 128) {
            size_t xb = ((size_t)(grp * 4 + erow) * 4096 + t) * 1024 + egu;
            xw0 = __ldg(g_xw + xb);
            xw1 = __ldg(g_xw + xb + 256);
            xw2 = __ldg(g_xw + xb + 512);
            xw3 = __ldg(g_xw + xb + 768);
            jv  = __ldg(g_j + ((size_t)(grp * 4 + erow) * 4096 + t) * 256 + egu);
        }

        // wait for this step's h buffer (skip t=0: preloaded)
        if (t > 0) {
            uint32_t mb = mbar_a + (p ? 8u : 0u);
            unsigned par = p ? par1 : par0;
            asm volatile(
                "{\n\t.reg .pred P;\n\t"
                "WL%=:\n\t"
                "mbarrier.try_wait.parity.acquire.cta.shared::cta.b64 P, [%0], %1, 0x989680;\n\t"
                "@P bra WD%=;\n\t"
                "bra WL%=;\n\t"
                "WD%=:\n\t}"
                :: "r"(mb), "r"(par) : "memory");
            if (p) par1 ^= 1; else par0 ^= 1;
            if (tid == 0)   // re-arm for this barrier's next phase (step t+2)
                asm volatile("mbarrier.arrive.expect_tx.shared.b64 _, [%0], %1;"
                             :: "r"(mb), "r"(4096) : "memory");
        }

        // GEMV: LDS.128 h broadcasts, each reused for 2 cols x 2 pairs
        ull acc[4][2];
        #pragma unroll
        for (int r = 0; r < 4; r++) { acc[r][0] = 0ull; acc[r][1] = 0ull; }
        const float* base = hb + ks * 128;
        #pragma unroll
        for (int r = 0; r < 4; r++) {
            const ulonglong2* hp = (const ulonglong2*)(base + r * 32);
            #pragma unroll
            for (int i = 0; i < 8; i++) {
                ulonglong2 hv = hp[i];   // pairs (k, k+1), (k+2, k+3)
                FMA2(acc[r][0], hv.x, w2[0][2 * i]);
                FMA2(acc[r][1], hv.x, w2[1][2 * i]);
                FMA2(acc[r][0], hv.y, w2[0][2 * i + 1]);
                FMA2(acc[r][1], hv.y, w2[1][2 * i + 1]);
            }
        }
        // reduce pairs, store per-(row,ks) partials for 2 adjacent cols
        #pragma unroll
        for (int r = 0; r < 4; r++) {
            float lo, hi, s0, s1;
            asm("mov.b64 {%0, %1}, %2;" : "=f"(lo), "=f"(hi) : "l"(acc[r][0]));
            s0 = lo + hi;
            asm("mov.b64 {%0, %1}, %2;" : "=f"(lo), "=f"(hi) : "l"(acc[r][1]));
            s1 = lo + hi;
            ull pk;
            asm("mov.b64 %0, {%1, %2};" : "=l"(pk) : "f"(s0), "f"(s1));
            *(ull*)&pb[r * 1024 + ks * 128 + col0] = pk;
        }

        if (tid >= 128) {
            // GEMV-only warps: post arrival, head straight to next wait
            asm volatile("bar.arrive 0, 512;" ::: "memory");
        } else {
            asm volatile("bar.sync 0, 512;" ::: "memory");
            // elementwise LSTM update (threads 0..127)
            const float* pr = pb + erow * 1024;
            float G0 = xw0, G1 = xw1, G2 = xw2, G3 = xw3;
            #pragma unroll
            for (int q = 0; q < 8; q++) {
                G0 += pr[q * 128 +   0 + eul];
                G1 += pr[q * 128 +  32 + eul];
                G2 += pr[q * 128 +  64 + eul];
                G3 += pr[q * 128 +  96 + eul];
            }
            float cc = c_st;
            float iv = sigf(G0 + cc * wc0);
            float fv = sigf(G1 + cc * wc1);
            float gv = tanhfast(G2);
            float ov = sigf(G3 + cc * wc2);
            float chat = fv * cc + iv * gv;
            float cn = jv * chat + (1.f - jv) * cc;
            float hh = ov * tanhfast(chat);
            float hprev = hb[cslot * 128 + erow * 32 + eul];
            float hn = jv * hh + (1.f - jv) * hprev;
            c_st = cn;
            if (t < 4095)
                hstage[(1 - p) * 128 + tid] = hn;
            else
                g_h[(grp * 4 + erow) * 256 + egu] = hn;
            asm volatile("bar.sync 1, 128;" ::: "memory");
            // threads 0..7 each push the CTA's 512B chunk to one peer CTA
            if (t < 4095 && tid < 8) {
                asm volatile("fence.proxy.async.shared::cta;" ::: "memory");
                uint32_t src  = hst_a + (uint32_t)((1 - p) * 512);
                uint32_t dstl = (p ? hb0_a : hb1_a) + (uint32_t)(cslot * 512);
                uint32_t mbl  = mbar_a + (p ? 0u : 8u);   // barrier of buffer 1-p
                uint32_t dst, mbr;
                asm("mapa.shared::cluster.u32 %0, %1, %2;" : "=r"(dst) : "r"(dstl), "r"(tid));
                asm("mapa.shared::cluster.u32 %0, %1, %2;" : "=r"(mbr) : "r"(mbl),  "r"(tid));
                asm volatile(
                    "cp.async.bulk.shared::cluster.shared::cta.mbarrier::complete_tx::bytes "
                    "[%0], [%1], %2, [%3];"
                    :: "r"(dst), "r"(src), "r"(512), "r"(mbr) : "memory");
            }
        }
    }

    asm volatile("barrier.cluster.arrive.aligned;" ::: "memory");
    asm volatile("barrier.cluster.wait.aligned;"   ::: "memory");
}

// ---------------- final: out = h_T @ Wlin + blin ----------------
__global__ void k_final(const float* __restrict__ Wlin,
                        const float* __restrict__ blin, float* __restrict__ out) {
    __shared__ float hsm[256];
    int b = blockIdx.x, d = threadIdx.x;   // 64 threads
    for (int i = d; i < 256; i += 64) hsm[i] = g_h[b * 256 + i];
    __syncthreads();
    float acc = blin[d];
    #pragma unroll 8
    for (int k = 0; k < 256; k++) acc += hsm[k] * Wlin[k * 64 + d];
    out[b * 64 + d] = acc;
}

// ---------------- launcher ----------------
extern "C" void kernel_launch(void* const* d_in, const int* in_sizes, int n_in,
                              void* d_out, int out_size) {
    (void)in_sizes; (void)n_in; (void)out_size;
    const float* ev   = (const float*)d_in[0];
    const float* vc   = (const float*)d_in[2];
    const float* vn   = (const float*)d_in[3];
    const float* h0   = (const float*)d_in[4];
    const float* c0   = (const float*)d_in[5];
    const float* Wx   = (const float*)d_in[6];
    const float* Wh   = (const float*)d_in[7];
    const float* Wc   = (const float*)d_in[8];
    const float* bias = (const float*)d_in[9];
    const float* Ve   = (const float*)d_in[10];
    const float* Vc   = (const float*)d_in[11];
    const float* Vn   = (const float*)d_in[12];
    const float* Wlin = (const float*)d_in[13];
    const float* blin = (const float*)d_in[14];
    const float* Wef1 = (const float*)d_in[15];
    const float* bef1 = (const float*)d_in[16];
    const float* Wef3 = (const float*)d_in[17];
    const float* bef3 = (const float*)d_in[18];
    float* out = (float*)d_out;

    cudaFuncSetAttribute(k_embed_u, cudaFuncAttributeMaxDynamicSharedMemorySize, 96256);
    cudaFuncSetAttribute(k_gemm,    cudaFuncAttributeMaxDynamicSharedMemorySize, 65536);

    void *px, *pu, *pxw, *pj;
    cudaGetSymbolAddress(&px,  g_x);
    cudaGetSymbolAddress(&pu,  g_u);
    cudaGetSymbolAddress(&pxw, g_xw);
    cudaGetSymbolAddress(&pj,  g_j);

    // 1: embeddings + u (fused)
    k_embed_u<<<MROWS / 32, 256, 96256>>>(ev, vc, vn, Ve, Vc, Vn, Wef1, bef1);
    // 2: xW = x @ Wx + bias            [M,1024]
    k_gemm<<<dim3(MROWS / 64, 16), 256, 65536>>>((const float*)px, Wx, bias,
                                                 (float*)pxw, 1024, 0);
    // 3: j = sigmoid(u @ Wef3 + bef3)  [M,256]
    k_gemm<<<dim3(MROWS / 64, 4), 256, 65536>>>((const float*)pu, Wef3, bef3,
                                                (float*)pj, 256, 2);
    // 4: recurrence (target of ncu capture)
    k_recur<<<128, 512>>>(h0, c0, Wh, Wc);
    // 5: output projection
    k_final<<<64, 64>>>(Wlin, blin, out);
}